// round 1
// baseline (speedup 1.0000x reference)
#include <cuda_runtime.h>
#include <math.h>

// ---------------------------------------------------------------------------
// Problem constants
//   feat:      [1,128,128,128]  (d_in[0])
//   lr_guide:  [1,128,128,128]  (d_in[1])
//   hr_guide:  [1,128,256,256]  (d_in[2])
//   W1 [386,256] b1[256] W2 [256,128] b2[128] W3 [128,32] b3[32]
//   out:       [1,32,256,256] fp32
// ---------------------------------------------------------------------------

#define H_LR 128
#define W_LR 128
#define NPIX_LR (H_LR * W_LR)        // 16384
#define H_HR 256
#define W_HR 256
#define NPTS (H_HR * W_HR)           // 65536

// Scratch (device globals: allocation-free per harness rules)
__device__ float g_h1f[NPIX_LR * 256];   // layer1 featc part per LR pixel   (16 MB)
__device__ float g_h1g[NPTS * 256];      // layer1 guide part per HR point   (64 MB)

// ---------------------------------------------------------------------------
// Generic layer-1 GEMM:  out[p][n] = sum_c A[p][c] * W[c*256 + n]
//   A[p][c] = (img1 && c>=128) ? img1[(c-128)*M + p] : img0[c*M + p]
// Tiles: BM=64, BN=64, BK=16, 256 threads, 4x4 per thread.
// ---------------------------------------------------------------------------
__global__ __launch_bounds__(256) void gemm_layer1(
    const float* __restrict__ img0,
    const float* __restrict__ img1,
    const float* __restrict__ W,
    float* __restrict__ out,
    int M, int K)
{
    __shared__ float As[16][65];   // [kk][m], padded
    __shared__ float Bs[16][64];   // [kk][n]

    const int tid = threadIdx.x;
    const int tx = tid & 15, ty = tid >> 4;
    const int m0 = blockIdx.x * 64;
    const int n0 = blockIdx.y * 64;

    float acc[4][4];
#pragma unroll
    for (int i = 0; i < 4; i++)
#pragma unroll
        for (int j = 0; j < 4; j++) acc[i][j] = 0.f;

    for (int k0 = 0; k0 < K; k0 += 16) {
#pragma unroll
        for (int i = 0; i < 4; i++) {
            int e = tid + 256 * i;         // 0..1023
            int m = e & 63, kk = e >> 6;
            int c = k0 + kk;
            const float* src = (img1 != nullptr && c >= 128)
                               ? (img1 + (c - 128) * M)
                               : (img0 + c * M);
            As[kk][m] = src[m0 + m];
        }
#pragma unroll
        for (int i = 0; i < 4; i++) {
            int e = tid + 256 * i;
            int n = e & 63, kk = e >> 6;
            Bs[kk][n] = W[(k0 + kk) * 256 + n0 + n];
        }
        __syncthreads();
#pragma unroll
        for (int kk = 0; kk < 16; kk++) {
            float a[4];
#pragma unroll
            for (int i = 0; i < 4; i++) a[i] = As[kk][ty * 4 + i];
            float4 bv = *(const float4*)&Bs[kk][tx * 4];
            float b[4] = {bv.x, bv.y, bv.z, bv.w};
#pragma unroll
            for (int i = 0; i < 4; i++)
#pragma unroll
                for (int j = 0; j < 4; j++)
                    acc[i][j] = fmaf(a[i], b[j], acc[i][j]);
        }
        __syncthreads();
    }
#pragma unroll
    for (int i = 0; i < 4; i++)
#pragma unroll
        for (int j = 0; j < 4; j++)
            out[(m0 + ty * 4 + i) * 256 + n0 + tx * 4 + j] = acc[i][j];
}

// ---------------------------------------------------------------------------
// Fused tail kernel. One block = 32 consecutive HR points (one Y row segment)
// = 128 MLP rows (4 quadrants each).
//   layer2: 128x128 = relu(h1)[128x256] @ W2[256x128]  (8x8 reg blocking)
//   layer3: 128x32  = relu(l2+b2)       @ W3[128x32]
//   blend:  softmax(gc) over 4 quadrants, output channel-major.
// Dynamic smem layout (floats):
//   A3   @0       128*129 = 16512
//   As   @16512   32*129  = 4128   (reused as C3s 128*33 = 4224)
//   Bs   @20736   32*128  = 4096
//   W3s  @24832   4096
//   b1s  @28928 256 | w384 @29184 256 | w385 @29440 256
//   b2s  @29696 128 | b3s @29824 32
//   rely @29856 128 | relx @29984 128 | gcs @30112 128 | wq @30240 128
//   nbr  @30368 128 (int)
// total 30496 floats = 121984 bytes
// ---------------------------------------------------------------------------
#define TAIL_SMEM_BYTES (30496 * 4)

__global__ __launch_bounds__(256) void fused_tail(
    const float* __restrict__ feat,
    const float* __restrict__ W1,
    const float* __restrict__ b1,
    const float* __restrict__ W2,
    const float* __restrict__ b2,
    const float* __restrict__ W3,
    const float* __restrict__ b3,
    float* __restrict__ out)
{
    extern __shared__ float sm[];
    float* A3   = sm;             // [k2][r] pitch 129
    float* As   = sm + 16512;     // [kk][r] pitch 129
    float* C3s  = sm + 16512;     // [r][n]  pitch 33 (reuses As)
    float* Bs   = sm + 20736;     // [kk][n] pitch 128
    float* W3s  = sm + 24832;     // [k2][n] 128x32
    float* b1s  = sm + 28928;
    float* w384 = sm + 29184;
    float* w385 = sm + 29440;
    float* b2s  = sm + 29696;
    float* b3s  = sm + 29824;
    float* rely = sm + 29856;
    float* relx = sm + 29984;
    float* gcs  = sm + 30112;
    float* wq   = sm + 30240;
    int*   nbr  = (int*)(sm + 30368);

    const int tid = threadIdx.x;
    const int p0  = blockIdx.x * 32;      // base point
    const int Y   = p0 >> 8;              // same for whole block
    const int Xb  = p0 & 255;

    // small constant vectors
    b1s[tid]  = b1[tid];
    w384[tid] = W1[384 * 256 + tid];
    w385[tid] = W1[385 * 256 + tid];
    if (tid < 128) b2s[tid] = b2[tid];
    if (tid < 32)  b3s[tid] = b3[tid];
#pragma unroll
    for (int i = 0; i < 16; i++) W3s[tid + 256 * i] = W3[tid + 256 * i];

    // per-row (point,quadrant) metadata + gating dot products
    if (tid < 128) {
        int pt = tid >> 2, q = tid & 3;
        int X = Xb + pt;
        int vx = (q & 2) ? 1 : -1;        // perturbs Y (H axis)
        int vy = (q & 1) ? 1 : -1;        // perturbs X (W axis)
        int iy = (Y + vx) >> 1;           // exact nearest-sample reduction
        int ix = (X + vy) >> 1;
        bool ok = ((unsigned)iy < (unsigned)H_LR) && ((unsigned)ix < (unsigned)W_LR);
        int np = iy * W_LR + ix;
        nbr[tid]  = ok ? np : -1;
        rely[tid] = ok ? ((float)(Y - 2 * iy) - 0.5f) : ((float)Y + 0.5f - 128.0f);
        relx[tid] = ok ? ((float)(X - 2 * ix) - 0.5f) : ((float)X + 0.5f - 128.0f);
        float g = 0.f;
        if (ok) {
            int bp = (Y >> 1) * W_LR + (X >> 1);
#pragma unroll
            for (int c = 0; c < 3; c++)
                g = fmaf(feat[(124 + c) * NPIX_LR + bp],
                         feat[(124 + c) * NPIX_LR + np], g);
        }
        gcs[tid] = g;
    }
    __syncthreads();

    if (tid < 32) {
        float g0 = gcs[tid * 4 + 0], g1 = gcs[tid * 4 + 1];
        float g2 = gcs[tid * 4 + 2], g3 = gcs[tid * 4 + 3];
        float m = fmaxf(fmaxf(g0, g1), fmaxf(g2, g3));
        float e0 = expf(g0 - m), e1 = expf(g1 - m), e2 = expf(g2 - m), e3 = expf(g3 - m);
        float inv = 1.0f / (e0 + e1 + e2 + e3);
        wq[tid * 4 + 0] = e0 * inv;
        wq[tid * 4 + 1] = e1 * inv;
        wq[tid * 4 + 2] = e2 * inv;
        wq[tid * 4 + 3] = e3 * inv;
    }
    __syncthreads();

    // ---- layer 2: [128 rows x 256] @ W2[256 x 128] ----
    const int tx = tid & 15, ty = tid >> 4;
    float acc[8][8];
#pragma unroll
    for (int i = 0; i < 8; i++)
#pragma unroll
        for (int j = 0; j < 8; j++) acc[i][j] = 0.f;

    for (int k0 = 0; k0 < 256; k0 += 32) {
        // stage relu(h1) chunk: As[kk][r]
#pragma unroll
        for (int i = 0; i < 16; i++) {
            int e = tid + 256 * i;        // 0..4095
            int kk = e & 31, r = e >> 5;
            int k = k0 + kk;
            int nb = nbr[r];
            float v = g_h1g[(p0 + (r >> 2)) * 256 + k] + b1s[k];
            v = fmaf(rely[r], w384[k], v);
            v = fmaf(relx[r], w385[k], v);
            if (nb >= 0) v += g_h1f[nb * 256 + k];
            As[kk * 129 + r] = fmaxf(v, 0.f);
        }
        // stage W2 chunk: Bs[kk][n]
#pragma unroll
        for (int i = 0; i < 16; i++) {
            int e = tid + 256 * i;
            int n = e & 127, kk = e >> 7;
            Bs[kk * 128 + n] = W2[(k0 + kk) * 128 + n];
        }
        __syncthreads();
#pragma unroll
        for (int kk = 0; kk < 32; kk++) {
            float a[8];
#pragma unroll
            for (int i = 0; i < 8; i++) a[i] = As[kk * 129 + ty * 8 + i];
            float4 bv0 = *(const float4*)&Bs[kk * 128 + tx * 8];
            float4 bv1 = *(const float4*)&Bs[kk * 128 + tx * 8 + 4];
            float b[8] = {bv0.x, bv0.y, bv0.z, bv0.w, bv1.x, bv1.y, bv1.z, bv1.w};
#pragma unroll
            for (int i = 0; i < 8; i++)
#pragma unroll
                for (int j = 0; j < 8; j++)
                    acc[i][j] = fmaf(a[i], b[j], acc[i][j]);
        }
        __syncthreads();
    }

    // relu(l2 + b2) -> A3 transposed [k2][r]
#pragma unroll
    for (int i = 0; i < 8; i++)
#pragma unroll
        for (int j = 0; j < 8; j++)
            A3[(tx * 8 + j) * 129 + (ty * 8 + i)] =
                fmaxf(acc[i][j] + b2s[tx * 8 + j], 0.f);
    __syncthreads();

    // ---- layer 3: [128 x 128] @ W3[128 x 32] ----
    {
        int r = tid >> 1;
        int nb0 = (tid & 1) * 16;
        float a3[16];
#pragma unroll
        for (int j = 0; j < 16; j++) a3[j] = 0.f;
        for (int k2 = 0; k2 < 128; k2++) {
            float av = A3[k2 * 129 + r];
            const float4* wp = (const float4*)&W3s[k2 * 32 + nb0];
#pragma unroll
            for (int j4 = 0; j4 < 4; j4++) {
                float4 w4 = wp[j4];
                a3[j4 * 4 + 0] = fmaf(av, w4.x, a3[j4 * 4 + 0]);
                a3[j4 * 4 + 1] = fmaf(av, w4.y, a3[j4 * 4 + 1]);
                a3[j4 * 4 + 2] = fmaf(av, w4.z, a3[j4 * 4 + 2]);
                a3[j4 * 4 + 3] = fmaf(av, w4.w, a3[j4 * 4 + 3]);
            }
        }
#pragma unroll
        for (int j = 0; j < 16; j++) C3s[r * 33 + nb0 + j] = a3[j];
    }
    __syncthreads();

    // ---- softmax blend + coalesced channel-major store ----
#pragma unroll
    for (int i = 0; i < 4; i++) {
        int idx = tid + 256 * i;          // 0..1023
        int pt = idx & 31, n = idx >> 5;
        float s = b3s[n];                 // sum(w)=1 so bias can be added post-blend
#pragma unroll
        for (int q = 0; q < 4; q++)
            s = fmaf(wq[pt * 4 + q], C3s[(pt * 4 + q) * 33 + n], s);
        out[n * NPTS + p0 + pt] = s;
    }
}

// ---------------------------------------------------------------------------
extern "C" void kernel_launch(void* const* d_in, const int* in_sizes, int n_in,
                              void* d_out, int out_size)
{
    const float* feat     = (const float*)d_in[0];
    const float* lr_guide = (const float*)d_in[1];
    const float* hr_guide = (const float*)d_in[2];
    const float* W1       = (const float*)d_in[3];
    const float* b1       = (const float*)d_in[4];
    const float* W2       = (const float*)d_in[5];
    const float* b2       = (const float*)d_in[6];
    const float* W3       = (const float*)d_in[7];
    const float* b3       = (const float*)d_in[8];
    float* out = (float*)d_out;

    void* h1f_p = nullptr;
    void* h1g_p = nullptr;
    cudaGetSymbolAddress(&h1f_p, g_h1f);
    cudaGetSymbolAddress(&h1g_p, g_h1g);

    // h1_feat[16384,256] = featc_T @ W1[0:256,:]
    {
        dim3 grid(NPIX_LR / 64, 256 / 64);
        gemm_layer1<<<grid, 256>>>(lr_guide, feat, W1, (float*)h1f_p, NPIX_LR, 256);
    }
    // h1_guide[65536,256] = hr_guide_T @ W1[256:384,:]
    {
        dim3 grid(NPTS / 64, 256 / 64);
        gemm_layer1<<<grid, 256>>>(hr_guide, nullptr, W1 + 256 * 256, (float*)h1g_p,
                                   NPTS, 128);
    }
    // fused tail
    {
        cudaFuncSetAttribute(fused_tail, cudaFuncAttributeMaxDynamicSharedMemorySize,
                             TAIL_SMEM_BYTES);
        fused_tail<<<NPTS / 32, 256, TAIL_SMEM_BYTES>>>(
            feat, W1, b1, W2, b2, W3, b3, out);
    }
}

// round 2
// speedup vs baseline: 1.0002x; 1.0002x over previous
#include <cuda_runtime.h>
#include <math.h>

// ---------------------------------------------------------------------------
// Problem constants
//   feat:      [1,128,128,128]  (d_in[0])
//   lr_guide:  [1,128,128,128]  (d_in[1])
//   hr_guide:  [1,128,256,256]  (d_in[2])
//   W1 [386,256] b1[256] W2 [256,128] b2[128] W3 [128,32] b3[32]
//   out:       [1,32,256,256] fp32
// ---------------------------------------------------------------------------

#define H_LR 128
#define W_LR 128
#define NPIX_LR (H_LR * W_LR)        // 16384
#define H_HR 256
#define W_HR 256
#define NPTS (H_HR * W_HR)           // 65536

// Scratch (device globals: allocation-free per harness rules)
__device__ float g_h1f[NPIX_LR * 256];   // layer1 featc part per LR pixel   (16 MB)
__device__ float g_h1g[NPTS * 256];      // layer1 guide part per HR point   (64 MB)

// ---------------------------------------------------------------------------
// Generic layer-1 GEMM:  out[p][n] = sum_c A[p][c] * W[c*256 + n]
//   A[p][c] = (img1 && c>=128) ? img1[(c-128)*M + p] : img0[c*M + p]
// Tiles: BM=64, BN=64, BK=16, 256 threads, 4x4 per thread.
// ---------------------------------------------------------------------------
__global__ __launch_bounds__(256) void gemm_layer1(
    const float* __restrict__ img0,
    const float* __restrict__ img1,
    const float* __restrict__ W,
    float* __restrict__ out,
    int M, int K)
{
    __shared__ float As[16][65];   // [kk][m], padded
    __shared__ float Bs[16][64];   // [kk][n]

    const int tid = threadIdx.x;
    const int tx = tid & 15, ty = tid >> 4;
    const int m0 = blockIdx.x * 64;
    const int n0 = blockIdx.y * 64;

    float acc[4][4];
#pragma unroll
    for (int i = 0; i < 4; i++)
#pragma unroll
        for (int j = 0; j < 4; j++) acc[i][j] = 0.f;

    for (int k0 = 0; k0 < K; k0 += 16) {
#pragma unroll
        for (int i = 0; i < 4; i++) {
            int e = tid + 256 * i;         // 0..1023
            int m = e & 63, kk = e >> 6;
            int c = k0 + kk;
            const float* src = (img1 != nullptr && c >= 128)
                               ? (img1 + (c - 128) * M)
                               : (img0 + c * M);
            As[kk][m] = src[m0 + m];
        }
#pragma unroll
        for (int i = 0; i < 4; i++) {
            int e = tid + 256 * i;
            int n = e & 63, kk = e >> 6;
            Bs[kk][n] = W[(k0 + kk) * 256 + n0 + n];
        }
        __syncthreads();
#pragma unroll
        for (int kk = 0; kk < 16; kk++) {
            float a[4];
#pragma unroll
            for (int i = 0; i < 4; i++) a[i] = As[kk][ty * 4 + i];
            float4 bv = *(const float4*)&Bs[kk][tx * 4];
            float b[4] = {bv.x, bv.y, bv.z, bv.w};
#pragma unroll
            for (int i = 0; i < 4; i++)
#pragma unroll
                for (int j = 0; j < 4; j++)
                    acc[i][j] = fmaf(a[i], b[j], acc[i][j]);
        }
        __syncthreads();
    }
#pragma unroll
    for (int i = 0; i < 4; i++)
#pragma unroll
        for (int j = 0; j < 4; j++)
            out[(m0 + ty * 4 + i) * 256 + n0 + tx * 4 + j] = acc[i][j];
}

// ---------------------------------------------------------------------------
// Fused tail kernel. One block = 32 consecutive HR points (one Y row segment)
// = 128 MLP rows (4 quadrants each).
//   layer2: 128x128 = relu(h1)[128x256] @ W2[256x128]  (8x8 reg blocking)
//   layer3: 128x32  = relu(l2+b2)       @ W3[128x32]
//   blend:  softmax(gc) over 4 quadrants, output channel-major.
// Dynamic smem layout (floats):
//   A3   @0       128*129 = 16512
//   As   @16512   32*129  = 4128   (reused as C3s 128*33 = 4224)
//   Bs   @20736   32*128  = 4096
//   W3s  @24832   4096
//   b1s  @28928 256 | w384 @29184 256 | w385 @29440 256
//   b2s  @29696 128 | b3s @29824 32
//   rely @29856 128 | relx @29984 128 | gcs @30112 128 | wq @30240 128
//   nbr  @30368 128 (int)
// total 30496 floats = 121984 bytes
// ---------------------------------------------------------------------------
#define TAIL_SMEM_BYTES (30496 * 4)

__global__ __launch_bounds__(256) void fused_tail(
    const float* __restrict__ feat,
    const float* __restrict__ W1,
    const float* __restrict__ b1,
    const float* __restrict__ W2,
    const float* __restrict__ b2,
    const float* __restrict__ W3,
    const float* __restrict__ b3,
    float* __restrict__ out)
{
    extern __shared__ float sm[];
    float* A3   = sm;             // [k2][r] pitch 129
    float* As   = sm + 16512;     // [kk][r] pitch 129
    float* C3s  = sm + 16512;     // [r][n]  pitch 33 (reuses As)
    float* Bs   = sm + 20736;     // [kk][n] pitch 128
    float* W3s  = sm + 24832;     // [k2][n] 128x32
    float* b1s  = sm + 28928;
    float* w384 = sm + 29184;
    float* w385 = sm + 29440;
    float* b2s  = sm + 29696;
    float* b3s  = sm + 29824;
    float* rely = sm + 29856;
    float* relx = sm + 29984;
    float* gcs  = sm + 30112;
    float* wq   = sm + 30240;
    int*   nbr  = (int*)(sm + 30368);

    const int tid = threadIdx.x;
    const int p0  = blockIdx.x * 32;      // base point
    const int Y   = p0 >> 8;              // same for whole block
    const int Xb  = p0 & 255;

    // small constant vectors
    b1s[tid]  = b1[tid];
    w384[tid] = W1[384 * 256 + tid];
    w385[tid] = W1[385 * 256 + tid];
    if (tid < 128) b2s[tid] = b2[tid];
    if (tid < 32)  b3s[tid] = b3[tid];
#pragma unroll
    for (int i = 0; i < 16; i++) W3s[tid + 256 * i] = W3[tid + 256 * i];

    // per-row (point,quadrant) metadata + gating dot products
    if (tid < 128) {
        int pt = tid >> 2, q = tid & 3;
        int X = Xb + pt;
        int vx = (q & 2) ? 1 : -1;        // perturbs Y (H axis)
        int vy = (q & 1) ? 1 : -1;        // perturbs X (W axis)
        int iy = (Y + vx) >> 1;           // exact nearest-sample reduction
        int ix = (X + vy) >> 1;
        bool ok = ((unsigned)iy < (unsigned)H_LR) && ((unsigned)ix < (unsigned)W_LR);
        int np = iy * W_LR + ix;
        nbr[tid]  = ok ? np : -1;
        rely[tid] = ok ? ((float)(Y - 2 * iy) - 0.5f) : ((float)Y + 0.5f - 128.0f);
        relx[tid] = ok ? ((float)(X - 2 * ix) - 0.5f) : ((float)X + 0.5f - 128.0f);
        float g = 0.f;
        if (ok) {
            int bp = (Y >> 1) * W_LR + (X >> 1);
#pragma unroll
            for (int c = 0; c < 3; c++)
                g = fmaf(feat[(124 + c) * NPIX_LR + bp],
                         feat[(124 + c) * NPIX_LR + np], g);
        }
        gcs[tid] = g;
    }
    __syncthreads();

    if (tid < 32) {
        float g0 = gcs[tid * 4 + 0], g1 = gcs[tid * 4 + 1];
        float g2 = gcs[tid * 4 + 2], g3 = gcs[tid * 4 + 3];
        float m = fmaxf(fmaxf(g0, g1), fmaxf(g2, g3));
        float e0 = expf(g0 - m), e1 = expf(g1 - m), e2 = expf(g2 - m), e3 = expf(g3 - m);
        float inv = 1.0f / (e0 + e1 + e2 + e3);
        wq[tid * 4 + 0] = e0 * inv;
        wq[tid * 4 + 1] = e1 * inv;
        wq[tid * 4 + 2] = e2 * inv;
        wq[tid * 4 + 3] = e3 * inv;
    }
    __syncthreads();

    // ---- layer 2: [128 rows x 256] @ W2[256 x 128] ----
    const int tx = tid & 15, ty = tid >> 4;
    float acc[8][8];
#pragma unroll
    for (int i = 0; i < 8; i++)
#pragma unroll
        for (int j = 0; j < 8; j++) acc[i][j] = 0.f;

    for (int k0 = 0; k0 < 256; k0 += 32) {
        // stage relu(h1) chunk: As[kk][r]
#pragma unroll
        for (int i = 0; i < 16; i++) {
            int e = tid + 256 * i;        // 0..4095
            int kk = e & 31, r = e >> 5;
            int k = k0 + kk;
            int nb = nbr[r];
            float v = g_h1g[(p0 + (r >> 2)) * 256 + k] + b1s[k];
            v = fmaf(rely[r], w384[k], v);
            v = fmaf(relx[r], w385[k], v);
            if (nb >= 0) v += g_h1f[nb * 256 + k];
            As[kk * 129 + r] = fmaxf(v, 0.f);
        }
        // stage W2 chunk: Bs[kk][n]
#pragma unroll
        for (int i = 0; i < 16; i++) {
            int e = tid + 256 * i;
            int n = e & 127, kk = e >> 7;
            Bs[kk * 128 + n] = W2[(k0 + kk) * 128 + n];
        }
        __syncthreads();
#pragma unroll
        for (int kk = 0; kk < 32; kk++) {
            float a[8];
#pragma unroll
            for (int i = 0; i < 8; i++) a[i] = As[kk * 129 + ty * 8 + i];
            float4 bv0 = *(const float4*)&Bs[kk * 128 + tx * 8];
            float4 bv1 = *(const float4*)&Bs[kk * 128 + tx * 8 + 4];
            float b[8] = {bv0.x, bv0.y, bv0.z, bv0.w, bv1.x, bv1.y, bv1.z, bv1.w};
#pragma unroll
            for (int i = 0; i < 8; i++)
#pragma unroll
                for (int j = 0; j < 8; j++)
                    acc[i][j] = fmaf(a[i], b[j], acc[i][j]);
        }
        __syncthreads();
    }

    // relu(l2 + b2) -> A3 transposed [k2][r]
#pragma unroll
    for (int i = 0; i < 8; i++)
#pragma unroll
        for (int j = 0; j < 8; j++)
            A3[(tx * 8 + j) * 129 + (ty * 8 + i)] =
                fmaxf(acc[i][j] + b2s[tx * 8 + j], 0.f);
    __syncthreads();

    // ---- layer 3: [128 x 128] @ W3[128 x 32] ----
    {
        int r = tid >> 1;
        int nb0 = (tid & 1) * 16;
        float a3[16];
#pragma unroll
        for (int j = 0; j < 16; j++) a3[j] = 0.f;
        for (int k2 = 0; k2 < 128; k2++) {
            float av = A3[k2 * 129 + r];
            const float4* wp = (const float4*)&W3s[k2 * 32 + nb0];
#pragma unroll
            for (int j4 = 0; j4 < 4; j4++) {
                float4 w4 = wp[j4];
                a3[j4 * 4 + 0] = fmaf(av, w4.x, a3[j4 * 4 + 0]);
                a3[j4 * 4 + 1] = fmaf(av, w4.y, a3[j4 * 4 + 1]);
                a3[j4 * 4 + 2] = fmaf(av, w4.z, a3[j4 * 4 + 2]);
                a3[j4 * 4 + 3] = fmaf(av, w4.w, a3[j4 * 4 + 3]);
            }
        }
#pragma unroll
        for (int j = 0; j < 16; j++) C3s[r * 33 + nb0 + j] = a3[j];
    }
    __syncthreads();

    // ---- softmax blend + coalesced channel-major store ----
#pragma unroll
    for (int i = 0; i < 4; i++) {
        int idx = tid + 256 * i;          // 0..1023
        int pt = idx & 31, n = idx >> 5;
        float s = b3s[n];                 // sum(w)=1 so bias can be added post-blend
#pragma unroll
        for (int q = 0; q < 4; q++)
            s = fmaf(wq[pt * 4 + q], C3s[(pt * 4 + q) * 33 + n], s);
        out[n * NPTS + p0 + pt] = s;
    }
}

// ---------------------------------------------------------------------------
extern "C" void kernel_launch(void* const* d_in, const int* in_sizes, int n_in,
                              void* d_out, int out_size)
{
    const float* feat     = (const float*)d_in[0];
    const float* lr_guide = (const float*)d_in[1];
    const float* hr_guide = (const float*)d_in[2];
    const float* W1       = (const float*)d_in[3];
    const float* b1       = (const float*)d_in[4];
    const float* W2       = (const float*)d_in[5];
    const float* b2       = (const float*)d_in[6];
    const float* W3       = (const float*)d_in[7];
    const float* b3       = (const float*)d_in[8];
    float* out = (float*)d_out;

    void* h1f_p = nullptr;
    void* h1g_p = nullptr;
    cudaGetSymbolAddress(&h1f_p, g_h1f);
    cudaGetSymbolAddress(&h1g_p, g_h1g);

    // h1_feat[16384,256] = featc_T @ W1[0:256,:]
    {
        dim3 grid(NPIX_LR / 64, 256 / 64);
        gemm_layer1<<<grid, 256>>>(lr_guide, feat, W1, (float*)h1f_p, NPIX_LR, 256);
    }
    // h1_guide[65536,256] = hr_guide_T @ W1[256:384,:]
    {
        dim3 grid(NPTS / 64, 256 / 64);
        gemm_layer1<<<grid, 256>>>(hr_guide, nullptr, W1 + 256 * 256, (float*)h1g_p,
                                   NPTS, 128);
    }
    // fused tail
    {
        cudaFuncSetAttribute(fused_tail, cudaFuncAttributeMaxDynamicSharedMemorySize,
                             TAIL_SMEM_BYTES);
        fused_tail<<<NPTS / 32, 256, TAIL_SMEM_BYTES>>>(
            feat, W1, b1, W2, b2, W3, b3, out);
    }
}

// round 3
// speedup vs baseline: 1.6352x; 1.6348x over previous
#include <cuda_runtime.h>
#include <math.h>

// ---------------------------------------------------------------------------
// Problem constants
//   feat:      [1,128,128,128]  (d_in[0])
//   lr_guide:  [1,128,128,128]  (d_in[1])
//   hr_guide:  [1,128,256,256]  (d_in[2])
//   W1 [386,256] b1[256] W2 [256,128] b2[128] W3 [128,32] b3[32]
//   out:       [1,32,256,256] fp32
// ---------------------------------------------------------------------------

#define H_LR 128
#define W_LR 128
#define NPIX_LR (H_LR * W_LR)        // 16384
#define H_HR 256
#define W_HR 256
#define NPTS (H_HR * W_HR)           // 65536

typedef unsigned long long ull;

// packed fp32x2 helpers (FFMA2 path — not emitted by ptxas from C++)
__device__ __forceinline__ ull pack2(float lo, float hi) {
    ull r; asm("mov.b64 %0, {%1,%2};" : "=l"(r) : "f"(lo), "f"(hi)); return r;
}
__device__ __forceinline__ ull fma2(ull a, ull b, ull c) {
    ull d; asm("fma.rn.f32x2 %0, %1, %2, %3;" : "=l"(d) : "l"(a), "l"(b), "l"(c));
    return d;
}
__device__ __forceinline__ float2 unpack2(ull v) {
    float2 f; asm("mov.b64 {%0,%1}, %2;" : "=f"(f.x), "=f"(f.y) : "l"(v)); return f;
}

// Scratch (device globals: allocation-free per harness rules)
__device__ float g_h1f[NPIX_LR * 256];   // layer1 featc part per LR pixel   (16 MB)
__device__ float g_h1g[NPTS * 256];      // layer1 guide part per HR point   (64 MB)

// ---------------------------------------------------------------------------
// Layer-1 GEMM:  out[p][n] = sum_c A[p][c] * W[c*256 + n]
//   A[p][c] = (img1 && c>=128) ? img1[(c-128)*M + p] : img0[c*M + p]
// BM=64, BN=64, BK=16, 256 threads, 4x4 per thread, packed f32x2 inner loop.
// ---------------------------------------------------------------------------
__global__ __launch_bounds__(256) void gemm_layer1(
    const float* __restrict__ img0,
    const float* __restrict__ img1,
    const float* __restrict__ W,
    float* __restrict__ out,
    int M, int K)
{
    __shared__ float As[16][68];   // [kk][m], pitch 68 (16B aligned rows)
    __shared__ float Bs[16][64];   // [kk][n]

    const int tid = threadIdx.x;
    const int tx = tid & 15, ty = tid >> 4;
    const int m0 = blockIdx.x * 64;
    const int n0 = blockIdx.y * 64;

    ull acc[2][4];   // rows packed pairwise: acc[i2][j] = rows (ty*4+2i2, +1), col tx*4+j
#pragma unroll
    for (int i = 0; i < 2; i++)
#pragma unroll
        for (int j = 0; j < 4; j++) acc[i][j] = pack2(0.f, 0.f);

    for (int k0 = 0; k0 < K; k0 += 16) {
#pragma unroll
        for (int i = 0; i < 4; i++) {
            int e = tid + 256 * i;         // 0..1023
            int m = e & 63, kk = e >> 6;
            int c = k0 + kk;
            const float* src = (img1 != nullptr && c >= 128)
                               ? (img1 + (c - 128) * M)
                               : (img0 + c * M);
            As[kk][m] = src[m0 + m];
        }
#pragma unroll
        for (int i = 0; i < 4; i++) {
            int e = tid + 256 * i;
            int n = e & 63, kk = e >> 6;
            Bs[kk][n] = W[(k0 + kk) * 256 + n0 + n];
        }
        __syncthreads();
#pragma unroll
        for (int kk = 0; kk < 16; kk++) {
            ulonglong2 ap = *(const ulonglong2*)&As[kk][ty * 4];
            float4 bv = *(const float4*)&Bs[kk][tx * 4];
            ull b0 = pack2(bv.x, bv.x), b1p = pack2(bv.y, bv.y);
            ull b2p = pack2(bv.z, bv.z), b3p = pack2(bv.w, bv.w);
            acc[0][0] = fma2(ap.x, b0, acc[0][0]);
            acc[0][1] = fma2(ap.x, b1p, acc[0][1]);
            acc[0][2] = fma2(ap.x, b2p, acc[0][2]);
            acc[0][3] = fma2(ap.x, b3p, acc[0][3]);
            acc[1][0] = fma2(ap.y, b0, acc[1][0]);
            acc[1][1] = fma2(ap.y, b1p, acc[1][1]);
            acc[1][2] = fma2(ap.y, b2p, acc[1][2]);
            acc[1][3] = fma2(ap.y, b3p, acc[1][3]);
        }
        __syncthreads();
    }
#pragma unroll
    for (int r = 0; r < 4; r++) {
        int i2 = r >> 1, half = r & 1;
        float4 o;
        float2 u0 = unpack2(acc[i2][0]);
        float2 u1 = unpack2(acc[i2][1]);
        float2 u2 = unpack2(acc[i2][2]);
        float2 u3 = unpack2(acc[i2][3]);
        o.x = half ? u0.y : u0.x;
        o.y = half ? u1.y : u1.x;
        o.z = half ? u2.y : u2.x;
        o.w = half ? u3.y : u3.x;
        *(float4*)&out[(m0 + ty * 4 + r) * 256 + n0 + tx * 4] = o;
    }
}

// ---------------------------------------------------------------------------
// Fused tail kernel. One block = 32 consecutive HR points = 128 MLP rows.
//   layer2: 128x128 = relu(h1)[128x256] @ W2[256x128]  (packed f32x2, 8x8)
//   layer3: 128x32  = relu(l2+b2)       @ W3[128x32]   (packed f32x2)
//   blend:  softmax(gc) over 4 quadrants, channel-major store.
//
// smem (floats):
//   A3   @0      128*130 = 16640
//   As   @16640  32*132  = 4224   (reused as C3s 128*33 = 4224)
//   Bs   @20864  32*128  = 4096
//   hg   @24960  32*33   = 1056
//   W3s  @26016  4096
//   b1s  @30112 256 | w384 @30368 256 | w385 @30624 256
//   b2s  @30880 128 | b3s @31008 32
//   rely @31040 128 | relx @31168 128 | gcs @31296 128 | wq @31424 128
//   nbr  @31552 128 (int)
// total 31680 floats = 126720 bytes
// ---------------------------------------------------------------------------
#define TAIL_SMEM_BYTES (31680 * 4)

__global__ __launch_bounds__(256) void fused_tail(
    const float* __restrict__ feat,
    const float* __restrict__ W1,
    const float* __restrict__ b1,
    const float* __restrict__ W2,
    const float* __restrict__ b2,
    const float* __restrict__ W3,
    const float* __restrict__ b3,
    float* __restrict__ out)
{
    extern __shared__ float sm[];
    float* A3   = sm;             // [k2][r] pitch 130
    float* As   = sm + 16640;     // [kk][r] pitch 132 (16B-aligned rows)
    float* C3s  = sm + 16640;     // [r][n]  pitch 33 (reuses As)
    float* Bs   = sm + 20864;     // [kk][n] pitch 128
    float* hg   = sm + 24960;     // [pt][kk] pitch 33 (h1g chunk + b1)
    float* W3s  = sm + 26016;     // [k2][n] 128x32
    float* b1s  = sm + 30112;
    float* w384 = sm + 30368;
    float* w385 = sm + 30624;
    float* b2s  = sm + 30880;
    float* b3s  = sm + 31008;
    float* rely = sm + 31040;
    float* relx = sm + 31168;
    float* gcs  = sm + 31296;
    float* wq   = sm + 31424;
    int*   nbr  = (int*)(sm + 31552);

    const int tid = threadIdx.x;
    const int p0  = blockIdx.x * 32;      // base point
    const int Y   = p0 >> 8;              // same for whole block
    const int Xb  = p0 & 255;

    // small constant vectors
    b1s[tid]  = b1[tid];
    w384[tid] = W1[384 * 256 + tid];
    w385[tid] = W1[385 * 256 + tid];
    if (tid < 128) b2s[tid] = b2[tid];
    if (tid < 32)  b3s[tid] = b3[tid];
#pragma unroll
    for (int i = 0; i < 16; i++) W3s[tid + 256 * i] = W3[tid + 256 * i];

    // per-row (point,quadrant) metadata + gating dot products
    if (tid < 128) {
        int pt = tid >> 2, q = tid & 3;
        int X = Xb + pt;
        int vx = (q & 2) ? 1 : -1;        // perturbs Y (H axis)
        int vy = (q & 1) ? 1 : -1;        // perturbs X (W axis)
        int iy = (Y + vx) >> 1;           // exact nearest-sample reduction
        int ix = (X + vy) >> 1;
        bool ok = ((unsigned)iy < (unsigned)H_LR) && ((unsigned)ix < (unsigned)W_LR);
        int np = iy * W_LR + ix;
        nbr[tid]  = ok ? np : -1;
        rely[tid] = ok ? ((float)(Y - 2 * iy) - 0.5f) : ((float)Y + 0.5f - 128.0f);
        relx[tid] = ok ? ((float)(X - 2 * ix) - 0.5f) : ((float)X + 0.5f - 128.0f);
        float g = 0.f;
        if (ok) {
            int bp = (Y >> 1) * W_LR + (X >> 1);
#pragma unroll
            for (int c = 0; c < 3; c++)
                g = fmaf(feat[(124 + c) * NPIX_LR + bp],
                         feat[(124 + c) * NPIX_LR + np], g);
        }
        gcs[tid] = g;
    }
    __syncthreads();

    if (tid < 32) {
        float g0 = gcs[tid * 4 + 0], g1 = gcs[tid * 4 + 1];
        float g2 = gcs[tid * 4 + 2], g3 = gcs[tid * 4 + 3];
        float m = fmaxf(fmaxf(g0, g1), fmaxf(g2, g3));
        float e0 = expf(g0 - m), e1 = expf(g1 - m), e2 = expf(g2 - m), e3 = expf(g3 - m);
        float inv = 1.0f / (e0 + e1 + e2 + e3);
        wq[tid * 4 + 0] = e0 * inv;
        wq[tid * 4 + 1] = e1 * inv;
        wq[tid * 4 + 2] = e2 * inv;
        wq[tid * 4 + 3] = e3 * inv;
    }

    // ---- layer 2: [128 rows x 256] @ W2[256 x 128], packed f32x2 ----
    const int tx = tid & 15, ty = tid >> 4;
    ull acc[4][8];   // acc[i2][j]: rows (ty*8+2*i2, +1), col tx*8+j
#pragma unroll
    for (int i = 0; i < 4; i++)
#pragma unroll
        for (int j = 0; j < 8; j++) acc[i][j] = pack2(0.f, 0.f);

    for (int k0 = 0; k0 < 256; k0 += 32) {
        __syncthreads();
        // stage h1g chunk (+b1) into hg[pt][kk]
        {
            int pt = tid >> 3, kq = (tid & 7) * 4;
            float4 v = *(const float4*)&g_h1g[(p0 + pt) * 256 + k0 + kq];
            hg[pt * 33 + kq + 0] = v.x + b1s[k0 + kq + 0];
            hg[pt * 33 + kq + 1] = v.y + b1s[k0 + kq + 1];
            hg[pt * 33 + kq + 2] = v.z + b1s[k0 + kq + 2];
            hg[pt * 33 + kq + 3] = v.w + b1s[k0 + kq + 3];
        }
        // stage W2 chunk: Bs[kk][n] (vectorized)
#pragma unroll
        for (int i = 0; i < 4; i++) {
            int e = tid + 256 * i;          // 0..1023 -> (kk, nq)
            int kk = e >> 5, nq = (e & 31) * 4;
            *(float4*)&Bs[kk * 128 + nq] =
                *(const float4*)&W2[(k0 + kk) * 128 + nq];
        }
        __syncthreads();
        // build relu(h1) chunk: As[kk][r]
#pragma unroll
        for (int i = 0; i < 4; i++) {
            int e = tid + 256 * i;          // 0..1023 -> (r, kq)
            int r = e >> 3, kq = (e & 7) * 4;
            int pt = r >> 2;
            int nb = nbr[r];
            float4 f;
            if (nb >= 0) f = *(const float4*)&g_h1f[nb * 256 + k0 + kq];
            else         f = make_float4(0.f, 0.f, 0.f, 0.f);
            float ry = rely[r], rx = relx[r];
#pragma unroll
            for (int t = 0; t < 4; t++) {
                int kk = kq + t;
                float v = hg[pt * 33 + kk];
                v = fmaf(ry, w384[k0 + kk], v);
                v = fmaf(rx, w385[k0 + kk], v);
                v += (&f.x)[t];
                As[kk * 132 + r] = fmaxf(v, 0.f);
            }
        }
        __syncthreads();
#pragma unroll
        for (int kk = 0; kk < 32; kk++) {
            ulonglong2 aA = *(const ulonglong2*)&As[kk * 132 + ty * 8];
            ulonglong2 aB = *(const ulonglong2*)&As[kk * 132 + ty * 8 + 4];
            ull a_pk[4] = {aA.x, aA.y, aB.x, aB.y};
            float4 bv0 = *(const float4*)&Bs[kk * 128 + tx * 8];
            float4 bv1 = *(const float4*)&Bs[kk * 128 + tx * 8 + 4];
            ull b_pk[8];
            b_pk[0] = pack2(bv0.x, bv0.x); b_pk[1] = pack2(bv0.y, bv0.y);
            b_pk[2] = pack2(bv0.z, bv0.z); b_pk[3] = pack2(bv0.w, bv0.w);
            b_pk[4] = pack2(bv1.x, bv1.x); b_pk[5] = pack2(bv1.y, bv1.y);
            b_pk[6] = pack2(bv1.z, bv1.z); b_pk[7] = pack2(bv1.w, bv1.w);
#pragma unroll
            for (int i = 0; i < 4; i++)
#pragma unroll
                for (int j = 0; j < 8; j++)
                    acc[i][j] = fma2(a_pk[i], b_pk[j], acc[i][j]);
        }
    }
    __syncthreads();

    // relu(l2 + b2) -> A3 transposed [k2][r] (float2 stores, rows packed)
#pragma unroll
    for (int j = 0; j < 8; j++) {
        int k2 = tx * 8 + j;
        float bb = b2s[k2];
#pragma unroll
        for (int i2 = 0; i2 < 4; i2++) {
            float2 u = unpack2(acc[i2][j]);
            float2 o;
            o.x = fmaxf(u.x + bb, 0.f);
            o.y = fmaxf(u.y + bb, 0.f);
            *(float2*)&A3[k2 * 130 + ty * 8 + 2 * i2] = o;
        }
    }
    __syncthreads();

    // ---- layer 3: [128 x 128] @ W3[128 x 32], packed f32x2 ----
    {
        int r = tid >> 1;
        int nb0 = (tid & 1) * 16;
        ull a3[8];
#pragma unroll
        for (int j = 0; j < 8; j++) a3[j] = pack2(0.f, 0.f);
        for (int k2 = 0; k2 < 128; k2++) {
            float av = A3[k2 * 130 + r];
            ull av2 = pack2(av, av);
            ulonglong2 w0 = *(const ulonglong2*)&W3s[k2 * 32 + nb0];
            ulonglong2 w1 = *(const ulonglong2*)&W3s[k2 * 32 + nb0 + 4];
            ulonglong2 w2 = *(const ulonglong2*)&W3s[k2 * 32 + nb0 + 8];
            ulonglong2 w3 = *(const ulonglong2*)&W3s[k2 * 32 + nb0 + 12];
            a3[0] = fma2(av2, w0.x, a3[0]);
            a3[1] = fma2(av2, w0.y, a3[1]);
            a3[2] = fma2(av2, w1.x, a3[2]);
            a3[3] = fma2(av2, w1.y, a3[3]);
            a3[4] = fma2(av2, w2.x, a3[4]);
            a3[5] = fma2(av2, w2.y, a3[5]);
            a3[6] = fma2(av2, w3.x, a3[6]);
            a3[7] = fma2(av2, w3.y, a3[7]);
        }
#pragma unroll
        for (int j = 0; j < 8; j++) {
            float2 u = unpack2(a3[j]);
            C3s[r * 33 + nb0 + 2 * j + 0] = u.x;
            C3s[r * 33 + nb0 + 2 * j + 1] = u.y;
        }
    }
    __syncthreads();

    // ---- softmax blend + coalesced channel-major store ----
#pragma unroll
    for (int i = 0; i < 4; i++) {
        int idx = tid + 256 * i;          // 0..1023
        int pt = idx & 31, n = idx >> 5;
        float s = b3s[n];                 // sum(w)=1 so bias can be added post-blend
#pragma unroll
        for (int q = 0; q < 4; q++)
            s = fmaf(wq[pt * 4 + q], C3s[(pt * 4 + q) * 33 + n], s);
        out[n * NPTS + p0 + pt] = s;
    }
}

// ---------------------------------------------------------------------------
extern "C" void kernel_launch(void* const* d_in, const int* in_sizes, int n_in,
                              void* d_out, int out_size)
{
    const float* feat     = (const float*)d_in[0];
    const float* lr_guide = (const float*)d_in[1];
    const float* hr_guide = (const float*)d_in[2];
    const float* W1       = (const float*)d_in[3];
    const float* b1       = (const float*)d_in[4];
    const float* W2       = (const float*)d_in[5];
    const float* b2       = (const float*)d_in[6];
    const float* W3       = (const float*)d_in[7];
    const float* b3       = (const float*)d_in[8];
    float* out = (float*)d_out;

    void* h1f_p = nullptr;
    void* h1g_p = nullptr;
    cudaGetSymbolAddress(&h1f_p, g_h1f);
    cudaGetSymbolAddress(&h1g_p, g_h1g);

    // h1_feat[16384,256] = featc_T @ W1[0:256,:]
    {
        dim3 grid(NPIX_LR / 64, 256 / 64);
        gemm_layer1<<<grid, 256>>>(lr_guide, feat, W1, (float*)h1f_p, NPIX_LR, 256);
    }
    // h1_guide[65536,256] = hr_guide_T @ W1[256:384,:]
    {
        dim3 grid(NPTS / 64, 256 / 64);
        gemm_layer1<<<grid, 256>>>(hr_guide, nullptr, W1 + 256 * 256, (float*)h1g_p,
                                   NPTS, 128);
    }
    // fused tail
    {
        cudaFuncSetAttribute(fused_tail, cudaFuncAttributeMaxDynamicSharedMemorySize,
                             TAIL_SMEM_BYTES);
        fused_tail<<<NPTS / 32, 256, TAIL_SMEM_BYTES>>>(
            feat, W1, b1, W2, b2, W3, b3, out);
    }
}

// round 4
// speedup vs baseline: 2.2842x; 1.3969x over previous
#include <cuda_runtime.h>
#include <math.h>

// ---------------------------------------------------------------------------
// Problem constants
//   feat:      [1,128,128,128]  (d_in[0])
//   lr_guide:  [1,128,128,128]  (d_in[1])
//   hr_guide:  [1,128,256,256]  (d_in[2])
//   W1 [386,256] b1[256] W2 [256,128] b2[128] W3 [128,32] b3[32]
//   out:       [1,32,256,256] fp32
// ---------------------------------------------------------------------------

#define H_LR 128
#define W_LR 128
#define NPIX_LR (H_LR * W_LR)        // 16384
#define H_HR 256
#define W_HR 256
#define NPTS (H_HR * W_HR)           // 65536

typedef unsigned long long ull;

// packed fp32x2 helpers (FFMA2 path — not emitted by ptxas from C++)
__device__ __forceinline__ ull pack2(float lo, float hi) {
    ull r; asm("mov.b64 %0, {%1,%2};" : "=l"(r) : "f"(lo), "f"(hi)); return r;
}
__device__ __forceinline__ ull fma2(ull a, ull b, ull c) {
    ull d; asm("fma.rn.f32x2 %0, %1, %2, %3;" : "=l"(d) : "l"(a), "l"(b), "l"(c));
    return d;
}
__device__ __forceinline__ float2 unpack2(ull v) {
    float2 f; asm("mov.b64 {%0,%1}, %2;" : "=f"(f.x), "=f"(f.y) : "l"(v)); return f;
}

// Scratch (device globals: allocation-free per harness rules)
__device__ float g_h1f[NPIX_LR * 256];   // layer1 featc part per LR pixel   (16 MB)
__device__ float g_h1g[NPTS * 256];      // layer1 guide part per HR point   (64 MB)

// ---------------------------------------------------------------------------
// Layer-1 GEMM:  out[p][n] = sum_c A[p][c] * W[c*256 + n]
//   A[p][c] = (img1 && c>=128) ? img1[(c-128)*M + p] : img0[c*M + p]
// BM=64, BN=64, BK=16, 256 threads, 4x4/thread, f32x2 inner, reg double-buffer.
// ---------------------------------------------------------------------------
__global__ __launch_bounds__(256) void gemm_layer1(
    const float* __restrict__ img0,
    const float* __restrict__ img1,
    const float* __restrict__ W,
    float* __restrict__ out,
    int M, int K)
{
    __shared__ float As[16][68];   // [kk][m], pitch 68 (16B aligned rows)
    __shared__ float Bs[16][64];   // [kk][n]

    const int tid = threadIdx.x;
    const int tx = tid & 15, ty = tid >> 4;
    const int m0 = blockIdx.x * 64;
    const int n0 = blockIdx.y * 64;

    ull acc[2][4];
#pragma unroll
    for (int i = 0; i < 2; i++)
#pragma unroll
        for (int j = 0; j < 4; j++) acc[i][j] = pack2(0.f, 0.f);

    float pa[4], pb[4];
    // prologue loads for k0 = 0
#pragma unroll
    for (int i = 0; i < 4; i++) {
        int e = tid + 256 * i;
        int m = e & 63, kk = e >> 6;
        const float* src = (img1 != nullptr && kk >= 128)
                           ? (img1 + (kk - 128) * M) : (img0 + kk * M);
        pa[i] = src[m0 + m];
        int n = e & 63;
        pb[i] = W[kk * 256 + n0 + n];
    }

    for (int k0 = 0; k0 < K; k0 += 16) {
        // commit staged registers to smem
#pragma unroll
        for (int i = 0; i < 4; i++) {
            int e = tid + 256 * i;
            int m = e & 63, kk = e >> 6;
            As[kk][m] = pa[i];
            int n = e & 63;
            Bs[kk][n] = pb[i];
        }
        __syncthreads();
        // prefetch next tile (overlaps with inner compute)
        if (k0 + 16 < K) {
#pragma unroll
            for (int i = 0; i < 4; i++) {
                int e = tid + 256 * i;
                int m = e & 63, kk = e >> 6;
                int c = k0 + 16 + kk;
                const float* src = (img1 != nullptr && c >= 128)
                                   ? (img1 + (c - 128) * M) : (img0 + c * M);
                pa[i] = src[m0 + m];
                int n = e & 63;
                pb[i] = W[c * 256 + n0 + n];
            }
        }
#pragma unroll
        for (int kk = 0; kk < 16; kk++) {
            ulonglong2 ap = *(const ulonglong2*)&As[kk][ty * 4];
            float4 bv = *(const float4*)&Bs[kk][tx * 4];
            ull b0 = pack2(bv.x, bv.x), b1p = pack2(bv.y, bv.y);
            ull b2p = pack2(bv.z, bv.z), b3p = pack2(bv.w, bv.w);
            acc[0][0] = fma2(ap.x, b0, acc[0][0]);
            acc[0][1] = fma2(ap.x, b1p, acc[0][1]);
            acc[0][2] = fma2(ap.x, b2p, acc[0][2]);
            acc[0][3] = fma2(ap.x, b3p, acc[0][3]);
            acc[1][0] = fma2(ap.y, b0, acc[1][0]);
            acc[1][1] = fma2(ap.y, b1p, acc[1][1]);
            acc[1][2] = fma2(ap.y, b2p, acc[1][2]);
            acc[1][3] = fma2(ap.y, b3p, acc[1][3]);
        }
        __syncthreads();
    }
#pragma unroll
    for (int r = 0; r < 4; r++) {
        int i2 = r >> 1, half = r & 1;
        float4 o;
        float2 u0 = unpack2(acc[i2][0]);
        float2 u1 = unpack2(acc[i2][1]);
        float2 u2 = unpack2(acc[i2][2]);
        float2 u3 = unpack2(acc[i2][3]);
        o.x = half ? u0.y : u0.x;
        o.y = half ? u1.y : u1.x;
        o.z = half ? u2.y : u2.x;
        o.w = half ? u3.y : u3.x;
        *(float4*)&out[(m0 + ty * 4 + r) * 256 + n0 + tx * 4] = o;
    }
}

// ---------------------------------------------------------------------------
// Fused tail kernel. One block = 32 consecutive HR points = 128 MLP rows.
// smem overlay (floats), total 26528 floats = 106112 B -> 2 blocks/SM:
//   phase A (layer2):  As @0 (32*132)  Bs @4224 (32*128)  hg @8320 (32*33)
//   phase B (layer3):  A3 @0 (128*130) W3s @16640 (4096)  C3s @20736 (128*33)
//   persistent @24960: b1s 256, w384 256, w385 256, b2s 128, b3s 32,
//                      rely 128, relx 128, gcs 128, wq 128, nbr 128(int)
// ---------------------------------------------------------------------------
#define TAIL_SMEM_BYTES (26528 * 4)

__global__ __launch_bounds__(256, 2) void fused_tail(
    const float* __restrict__ feat,
    const float* __restrict__ W1,
    const float* __restrict__ b1,
    const float* __restrict__ W2,
    const float* __restrict__ b2,
    const float* __restrict__ W3,
    const float* __restrict__ b3,
    float* __restrict__ out)
{
    extern __shared__ float sm[];
    float* A3   = sm;             // [k2][r] pitch 130 (phase B)
    float* As   = sm;             // [kk][r] pitch 132 (phase A)
    float* Bs   = sm + 4224;      // [kk][n] pitch 128 (phase A)
    float* hg   = sm + 8320;      // [pt][kk] pitch 33 (phase A)
    float* W3s  = sm + 16640;     // [k2][n] 128x32 (disjoint from phase A)
    float* C3s  = sm + 20736;     // [r][n] pitch 33 (phase B)
    float* b1s  = sm + 24960;
    float* w384 = sm + 25216;
    float* w385 = sm + 25472;
    float* b2s  = sm + 25728;
    float* b3s  = sm + 25856;
    float* rely = sm + 25888;
    float* relx = sm + 26016;
    float* gcs  = sm + 26144;
    float* wq   = sm + 26272;
    int*   nbr  = (int*)(sm + 26400);

    const int tid = threadIdx.x;
    const int p0  = blockIdx.x * 32;      // base point
    const int Y   = p0 >> 8;              // same for whole block
    const int Xb  = p0 & 255;

    // small constant vectors (W3s region is disjoint from phase A -> load now)
    b1s[tid]  = b1[tid];
    w384[tid] = W1[384 * 256 + tid];
    w385[tid] = W1[385 * 256 + tid];
    if (tid < 128) b2s[tid] = b2[tid];
    if (tid < 32)  b3s[tid] = b3[tid];
#pragma unroll
    for (int i = 0; i < 16; i++) W3s[tid + 256 * i] = W3[tid + 256 * i];

    // per-row (point,quadrant) metadata + gating dot products
    if (tid < 128) {
        int pt = tid >> 2, q = tid & 3;
        int X = Xb + pt;
        int vx = (q & 2) ? 1 : -1;        // perturbs Y (H axis)
        int vy = (q & 1) ? 1 : -1;        // perturbs X (W axis)
        int iy = (Y + vx) >> 1;           // exact nearest-sample reduction
        int ix = (X + vy) >> 1;
        bool ok = ((unsigned)iy < (unsigned)H_LR) && ((unsigned)ix < (unsigned)W_LR);
        int np = iy * W_LR + ix;
        nbr[tid]  = ok ? np : -1;
        rely[tid] = ok ? ((float)(Y - 2 * iy) - 0.5f) : ((float)Y + 0.5f - 128.0f);
        relx[tid] = ok ? ((float)(X - 2 * ix) - 0.5f) : ((float)X + 0.5f - 128.0f);
        float g = 0.f;
        if (ok) {
            int bp = (Y >> 1) * W_LR + (X >> 1);
#pragma unroll
            for (int c = 0; c < 3; c++)
                g = fmaf(feat[(124 + c) * NPIX_LR + bp],
                         feat[(124 + c) * NPIX_LR + np], g);
        }
        gcs[tid] = g;
    }
    __syncthreads();

    if (tid < 32) {
        float g0 = gcs[tid * 4 + 0], g1 = gcs[tid * 4 + 1];
        float g2 = gcs[tid * 4 + 2], g3 = gcs[tid * 4 + 3];
        float m = fmaxf(fmaxf(g0, g1), fmaxf(g2, g3));
        float e0 = expf(g0 - m), e1 = expf(g1 - m), e2 = expf(g2 - m), e3 = expf(g3 - m);
        float inv = 1.0f / (e0 + e1 + e2 + e3);
        wq[tid * 4 + 0] = e0 * inv;
        wq[tid * 4 + 1] = e1 * inv;
        wq[tid * 4 + 2] = e2 * inv;
        wq[tid * 4 + 3] = e3 * inv;
    }

    // loop-invariant indices for staging
    const int pt_h = tid >> 3;            // hg: point index
    const int kq   = (tid & 7) * 4;       // hg & As-build k-quad (same for all i)
    int rr[4], nbv[4];
#pragma unroll
    for (int i = 0; i < 4; i++) {
        rr[i]  = (tid >> 3) + 32 * i;     // As-build row
        nbv[i] = nbr[rr[i]];
    }

    // prologue prefetch for k0 = 0
    float4 pf_hg = *(const float4*)&g_h1g[(p0 + pt_h) * 256 + kq];
    float4 pf_f[4];
#pragma unroll
    for (int i = 0; i < 4; i++)
        pf_f[i] = (nbv[i] >= 0) ? *(const float4*)&g_h1f[nbv[i] * 256 + kq]
                                : make_float4(0.f, 0.f, 0.f, 0.f);

    // ---- layer 2: [128 rows x 256] @ W2[256 x 128], packed f32x2 ----
    const int tx = tid & 15, ty = tid >> 4;
    ull acc[4][8];
#pragma unroll
    for (int i = 0; i < 4; i++)
#pragma unroll
        for (int j = 0; j < 8; j++) acc[i][j] = pack2(0.f, 0.f);

    for (int k0 = 0; k0 < 256; k0 += 32) {
        __syncthreads();                  // prev inner done reading As/Bs/hg
        // commit prefetched hg chunk (+b1)
        hg[pt_h * 33 + kq + 0] = pf_hg.x + b1s[k0 + kq + 0];
        hg[pt_h * 33 + kq + 1] = pf_hg.y + b1s[k0 + kq + 1];
        hg[pt_h * 33 + kq + 2] = pf_hg.z + b1s[k0 + kq + 2];
        hg[pt_h * 33 + kq + 3] = pf_hg.w + b1s[k0 + kq + 3];
        // stage W2 chunk (L2-hot after first blocks)
#pragma unroll
        for (int i = 0; i < 4; i++) {
            int e = tid + 256 * i;
            int kk = e >> 5, nq = (e & 31) * 4;
            *(float4*)&Bs[kk * 128 + nq] =
                *(const float4*)&W2[(k0 + kk) * 128 + nq];
        }
        __syncthreads();                  // hg visible
        // build relu(h1) chunk from registers + smem (no gmem here)
#pragma unroll
        for (int i = 0; i < 4; i++) {
            int r = rr[i];
            float ryv = rely[r], rxv = relx[r];
            float hb = hg[(r >> 2) * 33 + kq];   // note: per-t below
#pragma unroll
            for (int t = 0; t < 4; t++) {
                int kk = kq + t;
                float v = hg[(r >> 2) * 33 + kk];
                v = fmaf(ryv, w384[k0 + kk], v);
                v = fmaf(rxv, w385[k0 + kk], v);
                v += (&pf_f[i].x)[t];
                As[kk * 132 + r] = fmaxf(v, 0.f);
            }
            (void)hb;
        }
        // prefetch next chunk (latency hidden under inner loop)
        if (k0 < 224) {
            int kn = k0 + 32;
            pf_hg = *(const float4*)&g_h1g[(p0 + pt_h) * 256 + kn + kq];
#pragma unroll
            for (int i = 0; i < 4; i++)
                pf_f[i] = (nbv[i] >= 0)
                          ? *(const float4*)&g_h1f[nbv[i] * 256 + kn + kq]
                          : make_float4(0.f, 0.f, 0.f, 0.f);
        }
        __syncthreads();                  // As visible
#pragma unroll
        for (int kk = 0; kk < 32; kk++) {
            ulonglong2 aA = *(const ulonglong2*)&As[kk * 132 + ty * 8];
            ulonglong2 aB = *(const ulonglong2*)&As[kk * 132 + ty * 8 + 4];
            ull a_pk[4] = {aA.x, aA.y, aB.x, aB.y};
            float4 bv0 = *(const float4*)&Bs[kk * 128 + tx * 8];
            float4 bv1 = *(const float4*)&Bs[kk * 128 + tx * 8 + 4];
            ull b_pk[8];
            b_pk[0] = pack2(bv0.x, bv0.x); b_pk[1] = pack2(bv0.y, bv0.y);
            b_pk[2] = pack2(bv0.z, bv0.z); b_pk[3] = pack2(bv0.w, bv0.w);
            b_pk[4] = pack2(bv1.x, bv1.x); b_pk[5] = pack2(bv1.y, bv1.y);
            b_pk[6] = pack2(bv1.z, bv1.z); b_pk[7] = pack2(bv1.w, bv1.w);
#pragma unroll
            for (int i = 0; i < 4; i++)
#pragma unroll
                for (int j = 0; j < 8; j++)
                    acc[i][j] = fma2(a_pk[i], b_pk[j], acc[i][j]);
        }
    }
    __syncthreads();                      // layer2 done; phase A smem free

    // relu(l2 + b2) -> A3 transposed [k2][r] (float2 stores, rows packed)
#pragma unroll
    for (int j = 0; j < 8; j++) {
        int k2 = tx * 8 + j;
        float bb = b2s[k2];
#pragma unroll
        for (int i2 = 0; i2 < 4; i2++) {
            float2 u = unpack2(acc[i2][j]);
            float2 o;
            o.x = fmaxf(u.x + bb, 0.f);
            o.y = fmaxf(u.y + bb, 0.f);
            *(float2*)&A3[k2 * 130 + ty * 8 + 2 * i2] = o;
        }
    }
    __syncthreads();

    // ---- layer 3: [128 x 128] @ W3[128 x 32], packed f32x2 ----
    {
        int r = tid >> 1;
        int nb0 = (tid & 1) * 16;
        ull a3[8];
#pragma unroll
        for (int j = 0; j < 8; j++) a3[j] = pack2(0.f, 0.f);
        for (int k2 = 0; k2 < 128; k2++) {
            float av = A3[k2 * 130 + r];
            ull av2 = pack2(av, av);
            ulonglong2 w0 = *(const ulonglong2*)&W3s[k2 * 32 + nb0];
            ulonglong2 w1 = *(const ulonglong2*)&W3s[k2 * 32 + nb0 + 4];
            ulonglong2 w2 = *(const ulonglong2*)&W3s[k2 * 32 + nb0 + 8];
            ulonglong2 w3 = *(const ulonglong2*)&W3s[k2 * 32 + nb0 + 12];
            a3[0] = fma2(av2, w0.x, a3[0]);
            a3[1] = fma2(av2, w0.y, a3[1]);
            a3[2] = fma2(av2, w1.x, a3[2]);
            a3[3] = fma2(av2, w1.y, a3[3]);
            a3[4] = fma2(av2, w2.x, a3[4]);
            a3[5] = fma2(av2, w2.y, a3[5]);
            a3[6] = fma2(av2, w3.x, a3[6]);
            a3[7] = fma2(av2, w3.y, a3[7]);
        }
#pragma unroll
        for (int j = 0; j < 8; j++) {
            float2 u = unpack2(a3[j]);
            C3s[r * 33 + nb0 + 2 * j + 0] = u.x;
            C3s[r * 33 + nb0 + 2 * j + 1] = u.y;
        }
    }
    __syncthreads();

    // ---- softmax blend + coalesced channel-major store ----
#pragma unroll
    for (int i = 0; i < 4; i++) {
        int idx = tid + 256 * i;          // 0..1023
        int pt = idx & 31, n = idx >> 5;
        float s = b3s[n];                 // sum(w)=1 so bias can be added post-blend
#pragma unroll
        for (int q = 0; q < 4; q++)
            s = fmaf(wq[pt * 4 + q], C3s[(pt * 4 + q) * 33 + n], s);
        out[n * NPTS + p0 + pt] = s;
    }
}

// ---------------------------------------------------------------------------
extern "C" void kernel_launch(void* const* d_in, const int* in_sizes, int n_in,
                              void* d_out, int out_size)
{
    const float* feat     = (const float*)d_in[0];
    const float* lr_guide = (const float*)d_in[1];
    const float* hr_guide = (const float*)d_in[2];
    const float* W1       = (const float*)d_in[3];
    const float* b1       = (const float*)d_in[4];
    const float* W2       = (const float*)d_in[5];
    const float* b2       = (const float*)d_in[6];
    const float* W3       = (const float*)d_in[7];
    const float* b3       = (const float*)d_in[8];
    float* out = (float*)d_out;

    void* h1f_p = nullptr;
    void* h1g_p = nullptr;
    cudaGetSymbolAddress(&h1f_p, g_h1f);
    cudaGetSymbolAddress(&h1g_p, g_h1g);

    // h1_feat[16384,256] = featc_T @ W1[0:256,:]
    {
        dim3 grid(NPIX_LR / 64, 256 / 64);
        gemm_layer1<<<grid, 256>>>(lr_guide, feat, W1, (float*)h1f_p, NPIX_LR, 256);
    }
    // h1_guide[65536,256] = hr_guide_T @ W1[256:384,:]
    {
        dim3 grid(NPTS / 64, 256 / 64);
        gemm_layer1<<<grid, 256>>>(hr_guide, nullptr, W1 + 256 * 256, (float*)h1g_p,
                                   NPTS, 128);
    }
    // fused tail
    {
        cudaFuncSetAttribute(fused_tail, cudaFuncAttributeMaxDynamicSharedMemorySize,
                             TAIL_SMEM_BYTES);
        fused_tail<<<NPTS / 32, 256, TAIL_SMEM_BYTES>>>(
            feat, W1, b1, W2, b2, W3, b3, out);
    }
}

// round 6
// speedup vs baseline: 2.4640x; 1.0787x over previous
#include <cuda_runtime.h>
#include <math.h>
#include <stdint.h>

// ---------------------------------------------------------------------------
// Problem constants
//   feat[1,128,128,128] lr_guide[1,128,128,128] hr_guide[1,128,256,256]
//   W1[386,256] b1[256] W2[256,128] b2[128] W3[128,32] b3[32]
//   out [1,32,256,256] fp32
// ---------------------------------------------------------------------------
#define H_LR 128
#define W_LR 128
#define NPIX_LR (H_LR * W_LR)        // 16384
#define H_HR 256
#define W_HR 256
#define NPTS (H_HR * W_HR)           // 65536

typedef unsigned long long ull;

// ---- packed fp32x2 helpers (FFMA2 path) -----------------------------------
__device__ __forceinline__ ull pack2(float lo, float hi) {
    ull r; asm("mov.b64 %0, {%1,%2};" : "=l"(r) : "f"(lo), "f"(hi)); return r;
}
__device__ __forceinline__ ull fma2(ull a, ull b, ull c) {
    ull d; asm("fma.rn.f32x2 %0, %1, %2, %3;" : "=l"(d) : "l"(a), "l"(b), "l"(c));
    return d;
}
__device__ __forceinline__ float2 unpack2(ull v) {
    float2 f; asm("mov.b64 {%0,%1}, %2;" : "=f"(f.x), "=f"(f.y) : "l"(v)); return f;
}

// ---- cp.async helpers -----------------------------------------------------
__device__ __forceinline__ uint32_t smem_u32(const void* p) {
    uint32_t a;
    asm("{ .reg .u64 t; cvta.to.shared.u64 t, %1; cvt.u32.u64 %0, t; }"
        : "=r"(a) : "l"(p));
    return a;
}
__device__ __forceinline__ void cp16(uint32_t dst, const void* src) {
    asm volatile("cp.async.ca.shared.global [%0], [%1], 16;"
                 :: "r"(dst), "l"(src));
}
#define CP_COMMIT() asm volatile("cp.async.commit_group;" ::: "memory")
#define CP_WAIT(n)  asm volatile("cp.async.wait_group %0;" :: "n"(n) : "memory")

// Scratch (device globals: allocation-free per harness rules)
__device__ float g_h1f[NPIX_LR * 256];   // layer1 featc part per LR pixel (16 MB)
__device__ float g_h1g[NPTS * 256];      // layer1 guide part per HR point (64 MB)

// ---------------------------------------------------------------------------
// Layer-1 GEMM:  out[p][n] = sum_c A[p][c] * W[c*256 + n]
//   A[p][c] = (img1 && c>=128) ? img1[(c-128)*M + p] : img0[c*M + p]
// BM=64, BN=64, BK=16, 256 threads, 4x4/thread, f32x2 inner,
// cp.async 2-stage smem double buffer.
// ---------------------------------------------------------------------------
__global__ __launch_bounds__(256) void gemm_layer1(
    const float* __restrict__ img0,
    const float* __restrict__ img1,
    const float* __restrict__ W,
    float* __restrict__ out,
    int M, int K)
{
    __shared__ float As[2][16][68];   // [buf][kk][m], pitch 68 (272B rows, 16B ok)
    __shared__ float Bs[2][16][64];   // [buf][kk][n]

    const int tid = threadIdx.x;
    const int tx = tid & 15, ty = tid >> 4;
    const int m0 = blockIdx.x * 64;
    const int n0 = blockIdx.y * 64;
    const int kk  = tid >> 4;          // staging channel within chunk
    const int l16 = tid & 15;          // staging 16B lane

    uint32_t a_dst[2], b_dst[2];
    a_dst[0] = smem_u32(&As[0][kk][l16 * 4]);
    a_dst[1] = smem_u32(&As[1][kk][l16 * 4]);
    b_dst[0] = smem_u32(&Bs[0][kk][l16 * 4]);
    b_dst[1] = smem_u32(&Bs[1][kk][l16 * 4]);

    ull acc[2][4];
#pragma unroll
    for (int i = 0; i < 2; i++)
#pragma unroll
        for (int j = 0; j < 4; j++) acc[i][j] = pack2(0.f, 0.f);

    const int nk = K >> 4;

    // prologue: stage 0
    {
        int c = kk;
        const float* srcA = (img1 != nullptr && c >= 128)
                            ? (img1 + (c - 128) * M) : (img0 + c * M);
        cp16(a_dst[0], srcA + m0 + l16 * 4);
        cp16(b_dst[0], W + c * 256 + n0 + l16 * 4);
        CP_COMMIT();
    }

    for (int i = 0; i < nk; i++) {
        if (i + 1 < nk) {
            int c = (i + 1) * 16 + kk;
            const float* srcA = (img1 != nullptr && c >= 128)
                                ? (img1 + (c - 128) * M) : (img0 + c * M);
            int buf = (i + 1) & 1;
            cp16(a_dst[buf], srcA + m0 + l16 * 4);
            cp16(b_dst[buf], W + c * 256 + n0 + l16 * 4);
            CP_COMMIT();
            CP_WAIT(1);
        } else {
            CP_WAIT(0);
        }
        __syncthreads();
        const float (*Ac)[68] = As[i & 1];
        const float (*Bc)[64] = Bs[i & 1];
#pragma unroll
        for (int k = 0; k < 16; k++) {
            ulonglong2 ap = *(const ulonglong2*)&Ac[k][ty * 4];
            float4 bv = *(const float4*)&Bc[k][tx * 4];
            ull b0 = pack2(bv.x, bv.x), b1p = pack2(bv.y, bv.y);
            ull b2p = pack2(bv.z, bv.z), b3p = pack2(bv.w, bv.w);
            acc[0][0] = fma2(ap.x, b0, acc[0][0]);
            acc[0][1] = fma2(ap.x, b1p, acc[0][1]);
            acc[0][2] = fma2(ap.x, b2p, acc[0][2]);
            acc[0][3] = fma2(ap.x, b3p, acc[0][3]);
            acc[1][0] = fma2(ap.y, b0, acc[1][0]);
            acc[1][1] = fma2(ap.y, b1p, acc[1][1]);
            acc[1][2] = fma2(ap.y, b2p, acc[1][2]);
            acc[1][3] = fma2(ap.y, b3p, acc[1][3]);
        }
        __syncthreads();
    }
#pragma unroll
    for (int r = 0; r < 4; r++) {
        int i2 = r >> 1, half = r & 1;
        float4 o;
        float2 u0 = unpack2(acc[i2][0]);
        float2 u1 = unpack2(acc[i2][1]);
        float2 u2 = unpack2(acc[i2][2]);
        float2 u3 = unpack2(acc[i2][3]);
        o.x = half ? u0.y : u0.x;
        o.y = half ? u1.y : u1.x;
        o.z = half ? u2.y : u2.x;
        o.w = half ? u3.y : u3.x;
        *(float4*)&out[(m0 + ty * 4 + r) * 256 + n0 + tx * 4] = o;
    }
}

// ---------------------------------------------------------------------------
// Fused tail. One block = 32 consecutive HR points = 128 MLP rows.
//   layer2: D[128,128] = relu(h1)[128,256] @ W2  (f32x2, 8x8/thread)
//   layer3: C3[128,32] = relu(D+b2)[128,128] @ W3 (f32x2 GEMM, k-split 2)
//   blend:  softmax over 4 quadrants, channel-major store.
//
// smem byte map (106112 total):
//   phase A: As @0 (32x132 = 16896B), Bs @16896 (32x128 = 16384B),
//            hg @33280 (32x256 fp32 = 32768B)                end 66048
//   phase B: A3 @0 (128x132 = 67584B)
//   W3s @67584 (16384B)  C3s @83968 (128x33 = 16896B)        end 100864
//   persistent @100864: w384 1024 | w385 @101888 1024 | b2s @102912 512 |
//     b3s @103424 128 | rely @103552 512 | relx @104064 512 |
//     gcs @104576 512 | wq @105088 512 | nbr @105600 512     end 106112
// ---------------------------------------------------------------------------
#define TAIL_SMEM_BYTES 106112

__global__ __launch_bounds__(256, 2) void fused_tail(
    const float* __restrict__ feat,
    const float* __restrict__ W1,
    const float* __restrict__ b1,
    const float* __restrict__ W2,
    const float* __restrict__ b2,
    const float* __restrict__ W3,
    const float* __restrict__ b3,
    float* __restrict__ out)
{
    extern __shared__ char smem[];
    float* As    = (float*)(smem);            // [kk][r] pitch 132 (phase A)
    float* Bs    = (float*)(smem + 16896);    // [kk][n] pitch 128 (phase A)
    float* hg    = (float*)(smem + 33280);    // [pt][256] (phase A)
    float* A3    = (float*)(smem);            // [k2][r] pitch 132 (phase B)
    float* W3s   = (float*)(smem + 67584);    // [k2][32]
    float* C3s   = (float*)(smem + 83968);    // [r][33]
    float* w384s = (float*)(smem + 100864);
    float* w385s = (float*)(smem + 101888);
    float* b2s   = (float*)(smem + 102912);
    float* b3s   = (float*)(smem + 103424);
    float* rely  = (float*)(smem + 103552);
    float* relx  = (float*)(smem + 104064);
    float* gcs   = (float*)(smem + 104576);
    float* wq    = (float*)(smem + 105088);
    int*   nbr   = (int*)  (smem + 105600);

    const int tid = threadIdx.x;
    const int p0  = blockIdx.x * 32;
    const int Y   = p0 >> 8;
    const int Xb  = p0 & 255;

    // small vectors (W3s region is disjoint from phase A -> load now)
    w384s[tid] = W1[384 * 256 + tid];
    w385s[tid] = W1[385 * 256 + tid];
    if (tid < 128) b2s[tid] = b2[tid];
    if (tid < 32)  b3s[tid] = b3[tid];
#pragma unroll
    for (int i = 0; i < 16; i++) W3s[tid + 256 * i] = W3[tid + 256 * i];

    // per-row metadata + gating dots
    if (tid < 128) {
        int pt = tid >> 2, q = tid & 3;
        int X = Xb + pt;
        int vx = (q & 2) ? 1 : -1;        // perturbs Y (H axis)
        int vy = (q & 1) ? 1 : -1;        // perturbs X (W axis)
        int iy = (Y + vx) >> 1;           // exact nearest-sample reduction
        int ix = (X + vy) >> 1;
        bool ok = ((unsigned)iy < (unsigned)H_LR) && ((unsigned)ix < (unsigned)W_LR);
        int np = iy * W_LR + ix;
        nbr[tid]  = ok ? np : -1;
        rely[tid] = ok ? ((float)(Y - 2 * iy) - 0.5f) : ((float)Y + 0.5f - 128.0f);
        relx[tid] = ok ? ((float)(X - 2 * ix) - 0.5f) : ((float)X + 0.5f - 128.0f);
        float g = 0.f;
        if (ok) {
            int bp = (Y >> 1) * W_LR + (X >> 1);
#pragma unroll
            for (int c = 0; c < 3; c++)
                g = fmaf(feat[(124 + c) * NPIX_LR + bp],
                         feat[(124 + c) * NPIX_LR + np], g);
        }
        gcs[tid] = g;
    }

    // stage full hg (+b1) once: 32 pts x 256 k
#pragma unroll
    for (int i = 0; i < 8; i++) {
        int e = tid + 256 * i;            // float4 slots
        int pt = e >> 6, kq = (e & 63) * 4;
        float4 v = *(const float4*)&g_h1g[(p0 + pt) * 256 + kq];
        float4 bv = *(const float4*)&b1[kq];
        v.x += bv.x; v.y += bv.y; v.z += bv.z; v.w += bv.w;
        *(float4*)&hg[pt * 256 + kq] = v;
    }
    __syncthreads();

    if (tid < 32) {
        float g0 = gcs[tid * 4 + 0], g1 = gcs[tid * 4 + 1];
        float g2 = gcs[tid * 4 + 2], g3 = gcs[tid * 4 + 3];
        float m = fmaxf(fmaxf(g0, g1), fmaxf(g2, g3));
        float e0 = expf(g0 - m), e1 = expf(g1 - m), e2 = expf(g2 - m), e3 = expf(g3 - m);
        float inv = 1.0f / (e0 + e1 + e2 + e3);
        wq[tid * 4 + 0] = e0 * inv;
        wq[tid * 4 + 1] = e1 * inv;
        wq[tid * 4 + 2] = e2 * inv;
        wq[tid * 4 + 3] = e3 * inv;
    }

    // staging indices (loop-invariant)
    const int kq = (tid & 7) * 4;
    int rr[4], nbv[4];
#pragma unroll
    for (int i = 0; i < 4; i++) {
        rr[i]  = (tid >> 3) + 32 * i;
        nbv[i] = nbr[rr[i]];
    }
    // prologue prefetch of g_h1f for chunk 0
    float4 pf_f[4];
#pragma unroll
    for (int i = 0; i < 4; i++)
        pf_f[i] = (nbv[i] >= 0) ? *(const float4*)&g_h1f[nbv[i] * 256 + kq]
                                : make_float4(0.f, 0.f, 0.f, 0.f);

    // ---- layer 2: 8 chunks of K=32 ----
    const int tx = tid & 15, ty = tid >> 4;
    ull acc[4][8];
#pragma unroll
    for (int i = 0; i < 4; i++)
#pragma unroll
        for (int j = 0; j < 8; j++) acc[i][j] = pack2(0.f, 0.f);

    for (int k0 = 0; k0 < 256; k0 += 32) {
        __syncthreads();                  // prev inner done reading As/Bs
        // build relu(h1) chunk: As[kk][r]
#pragma unroll
        for (int i = 0; i < 4; i++) {
            int r = rr[i];
            float ryv = rely[r], rxv = relx[r];
            const float* hrow = hg + (r >> 2) * 256 + k0;
#pragma unroll
            for (int t = 0; t < 4; t++) {
                int kk = kq + t;
                float v = hrow[kk];
                v = fmaf(ryv, w384s[k0 + kk], v);
                v = fmaf(rxv, w385s[k0 + kk], v);
                v += (&pf_f[i].x)[t];
                As[kk * 132 + r] = fmaxf(v, 0.f);
            }
        }
        // stage W2 chunk (L2-hot)
#pragma unroll
        for (int i = 0; i < 4; i++) {
            int e = tid + 256 * i;
            int kk = e >> 5, nq = (e & 31) * 4;
            *(float4*)&Bs[kk * 128 + nq] =
                *(const float4*)&W2[(k0 + kk) * 128 + nq];
        }
        // prefetch next g_h1f chunk
        if (k0 < 224) {
            int kn = k0 + 32;
#pragma unroll
            for (int i = 0; i < 4; i++)
                pf_f[i] = (nbv[i] >= 0)
                          ? *(const float4*)&g_h1f[nbv[i] * 256 + kn + kq]
                          : make_float4(0.f, 0.f, 0.f, 0.f);
        }
        __syncthreads();                  // As/Bs visible
#pragma unroll
        for (int kk = 0; kk < 32; kk++) {
            ulonglong2 aA = *(const ulonglong2*)&As[kk * 132 + ty * 8];
            ulonglong2 aB = *(const ulonglong2*)&As[kk * 132 + ty * 8 + 4];
            ull a_pk[4] = {aA.x, aA.y, aB.x, aB.y};
            float4 bv0 = *(const float4*)&Bs[kk * 128 + tx * 8];
            float4 bv1 = *(const float4*)&Bs[kk * 128 + tx * 8 + 4];
            ull b_pk[8];
            b_pk[0] = pack2(bv0.x, bv0.x); b_pk[1] = pack2(bv0.y, bv0.y);
            b_pk[2] = pack2(bv0.z, bv0.z); b_pk[3] = pack2(bv0.w, bv0.w);
            b_pk[4] = pack2(bv1.x, bv1.x); b_pk[5] = pack2(bv1.y, bv1.y);
            b_pk[6] = pack2(bv1.z, bv1.z); b_pk[7] = pack2(bv1.w, bv1.w);
#pragma unroll
            for (int i = 0; i < 4; i++)
#pragma unroll
                for (int j = 0; j < 8; j++)
                    acc[i][j] = fma2(a_pk[i], b_pk[j], acc[i][j]);
        }
    }
    __syncthreads();                      // layer2 done; phase A smem free

    // relu(l2 + b2) -> A3 transposed [k2][r] (float2 stores, rows packed)
#pragma unroll
    for (int j = 0; j < 8; j++) {
        int k2 = tx * 8 + j;
        float bb = b2s[k2];
#pragma unroll
        for (int i2 = 0; i2 < 4; i2++) {
            float2 u = unpack2(acc[i2][j]);
            float2 o;
            o.x = fmaxf(u.x + bb, 0.f);
            o.y = fmaxf(u.y + bb, 0.f);
            *(float2*)&A3[k2 * 132 + ty * 8 + 2 * i2] = o;
        }
    }
    __syncthreads();

    // ---- layer 3: C3[128,32] = A3^T @ W3, k-split GEMM ----
    // 256 threads = kh(2) x rg(16) x cg(8); tile 8 rows x 4 cols per thread.
    {
        const int kh = tid >> 7;          // k-half
        const int rem = tid & 127;
        const int rg = rem >> 3;          // rows rg*8..+7
        const int cg = rem & 7;           // cols cg*4..+3
        ull a3[4][4];                     // [row pair][col]
#pragma unroll
        for (int p = 0; p < 4; p++)
#pragma unroll
            for (int j = 0; j < 4; j++) a3[p][j] = pack2(0.f, 0.f);

        const float* a_base = A3 + (uint32_t)kh * 64 * 132 + rg * 8;
        const float* w_base = W3s + (uint32_t)kh * 64 * 32 + cg * 4;
        for (int kt = 0; kt < 64; kt++) {
            ulonglong2 aA = *(const ulonglong2*)(a_base + kt * 132);
            ulonglong2 aB = *(const ulonglong2*)(a_base + kt * 132 + 4);
            float4 wv = *(const float4*)(w_base + kt * 32);
            ull w0 = pack2(wv.x, wv.x), w1 = pack2(wv.y, wv.y);
            ull w2 = pack2(wv.z, wv.z), w3v = pack2(wv.w, wv.w);
            ull ap[4] = {aA.x, aA.y, aB.x, aB.y};
#pragma unroll
            for (int p = 0; p < 4; p++) {
                a3[p][0] = fma2(ap[p], w0, a3[p][0]);
                a3[p][1] = fma2(ap[p], w1, a3[p][1]);
                a3[p][2] = fma2(ap[p], w2, a3[p][2]);
                a3[p][3] = fma2(ap[p], w3v, a3[p][3]);
            }
        }
        // reduce two k-halves via C3s
        if (kh == 1) {
#pragma unroll
            for (int p = 0; p < 4; p++)
#pragma unroll
                for (int j = 0; j < 4; j++) {
                    float2 u = unpack2(a3[p][j]);
                    C3s[(rg * 8 + 2 * p) * 33 + cg * 4 + j]     = u.x;
                    C3s[(rg * 8 + 2 * p + 1) * 33 + cg * 4 + j] = u.y;
                }
        }
        __syncthreads();
        if (kh == 0) {
#pragma unroll
            for (int p = 0; p < 4; p++)
#pragma unroll
                for (int j = 0; j < 4; j++) {
                    float2 u = unpack2(a3[p][j]);
                    C3s[(rg * 8 + 2 * p) * 33 + cg * 4 + j]     += u.x;
                    C3s[(rg * 8 + 2 * p + 1) * 33 + cg * 4 + j] += u.y;
                }
        }
        __syncthreads();
    }

    // ---- softmax blend + coalesced channel-major store ----
#pragma unroll
    for (int i = 0; i < 4; i++) {
        int idx = tid + 256 * i;
        int pt = idx & 31, n = idx >> 5;
        float s = b3s[n];                 // sum(w)=1 -> bias post-blend
#pragma unroll
        for (int q = 0; q < 4; q++)
            s = fmaf(wq[pt * 4 + q], C3s[(pt * 4 + q) * 33 + n], s);
        out[n * NPTS + p0 + pt] = s;
    }
}

// ---------------------------------------------------------------------------
extern "C" void kernel_launch(void* const* d_in, const int* in_sizes, int n_in,
                              void* d_out, int out_size)
{
    const float* feat     = (const float*)d_in[0];
    const float* lr_guide = (const float*)d_in[1];
    const float* hr_guide = (const float*)d_in[2];
    const float* W1       = (const float*)d_in[3];
    const float* b1       = (const float*)d_in[4];
    const float* W2       = (const float*)d_in[5];
    const float* b2       = (const float*)d_in[6];
    const float* W3       = (const float*)d_in[7];
    const float* b3       = (const float*)d_in[8];
    float* out = (float*)d_out;

    void* h1f_p = nullptr;
    void* h1g_p = nullptr;
    cudaGetSymbolAddress(&h1f_p, g_h1f);
    cudaGetSymbolAddress(&h1g_p, g_h1g);

    // h1_feat[16384,256] = featc_T @ W1[0:256,:]
    {
        dim3 grid(NPIX_LR / 64, 256 / 64);
        gemm_layer1<<<grid, 256>>>(lr_guide, feat, W1, (float*)h1f_p, NPIX_LR, 256);
    }
    // h1_guide[65536,256] = hr_guide_T @ W1[256:384,:]
    {
        dim3 grid(NPTS / 64, 256 / 64);
        gemm_layer1<<<grid, 256>>>(hr_guide, nullptr, W1 + 256 * 256, (float*)h1g_p,
                                   NPTS, 128);
    }
    // fused tail
    {
        cudaFuncSetAttribute(fused_tail, cudaFuncAttributeMaxDynamicSharedMemorySize,
                             TAIL_SMEM_BYTES);
        fused_tail<<<NPTS / 32, 256, TAIL_SMEM_BYTES>>>(
            feat, W1, b1, W2, b2, W3, b3, out);
    }
}

// round 7
// speedup vs baseline: 2.8754x; 1.1669x over previous
#include <cuda_runtime.h>
#include <math.h>
#include <stdint.h>

// ---------------------------------------------------------------------------
// Problem constants
//   feat[1,128,128,128] lr_guide[1,128,128,128] hr_guide[1,128,256,256]
//   W1[386,256] b1[256] W2[256,128] b2[128] W3[128,32] b3[32]
//   out [1,32,256,256] fp32
// ---------------------------------------------------------------------------
#define H_LR 128
#define W_LR 128
#define NPIX_LR (H_LR * W_LR)        // 16384
#define H_HR 256
#define W_HR 256
#define NPTS (H_HR * W_HR)           // 65536

typedef unsigned long long ull;

// ---- packed fp32x2 helpers (FFMA2 path) -----------------------------------
__device__ __forceinline__ ull pack2(float lo, float hi) {
    ull r; asm("mov.b64 %0, {%1,%2};" : "=l"(r) : "f"(lo), "f"(hi)); return r;
}
__device__ __forceinline__ ull fma2(ull a, ull b, ull c) {
    ull d; asm("fma.rn.f32x2 %0, %1, %2, %3;" : "=l"(d) : "l"(a), "l"(b), "l"(c));
    return d;
}
__device__ __forceinline__ float2 unpack2(ull v) {
    float2 f; asm("mov.b64 {%0,%1}, %2;" : "=f"(f.x), "=f"(f.y) : "l"(v)); return f;
}

// ---- cp.async helpers -----------------------------------------------------
__device__ __forceinline__ uint32_t smem_u32(const void* p) {
    uint32_t a;
    asm("{ .reg .u64 t; cvta.to.shared.u64 t, %1; cvt.u32.u64 %0, t; }"
        : "=r"(a) : "l"(p));
    return a;
}
__device__ __forceinline__ void cp16(uint32_t dst, const void* src) {
    asm volatile("cp.async.ca.shared.global [%0], [%1], 16;"
                 :: "r"(dst), "l"(src));
}
#define CP_COMMIT() asm volatile("cp.async.commit_group;" ::: "memory")
#define CP_WAIT(n)  asm volatile("cp.async.wait_group %0;" :: "n"(n) : "memory")

// 16B-unit XOR swizzle: distinct bank-quads within an 8-thread LDS phase
__device__ __forceinline__ int swz(int u) { return u ^ (u >> 3); }

// Scratch (device globals: allocation-free per harness rules)
__device__ float g_h1f[NPIX_LR * 256];   // layer1 featc part per LR pixel (16 MB)
__device__ float g_h1g[NPTS * 256];      // layer1 guide part per HR point (64 MB)

// ---------------------------------------------------------------------------
// Layer-1 GEMM, wide tiles:  out[p][n] = sum_c A[p][c] * W[c*256 + n]
//   A[p][c] = (img1 && c>=128) ? img1[(c-128)*M + p] : img0[c*M + p]
// BM=128, BN=128, BK=16, 256 threads, 8x8/thread (f32x2),
// cp.async 2-stage double buffer, XOR-swizzled smem units.
// ---------------------------------------------------------------------------
__global__ __launch_bounds__(256, 2) void gemm_layer1(
    const float* __restrict__ img0,
    const float* __restrict__ img1,
    const float* __restrict__ W,
    float* __restrict__ out,
    int M, int K)
{
    __shared__ float As[2][16 * 128];
    __shared__ float Bs[2][16 * 128];

    const int tid = threadIdx.x;
    const int tx = tid & 15, ty = tid >> 4;
    const int m0 = blockIdx.x * 128;
    const int n0 = blockIdx.y * 128;
    const int ch = tid >> 4;           // staging channel
    const int lane = tid & 15;         // staging lane (8 floats)
    const int pu0 = swz(2 * lane), pu1 = swz(2 * lane + 1);

    uint32_t aS[2], bS[2];
    aS[0] = smem_u32(&As[0][ch * 128]);
    aS[1] = smem_u32(&As[1][ch * 128]);
    bS[0] = smem_u32(&Bs[0][ch * 128]);
    bS[1] = smem_u32(&Bs[1][ch * 128]);

    ull acc[4][8];
#pragma unroll
    for (int i = 0; i < 4; i++)
#pragma unroll
        for (int j = 0; j < 8; j++) acc[i][j] = pack2(0.f, 0.f);

    const int nk = K >> 4;

    // prologue: stage chunk 0
    {
        int c = ch;
        const float* srcA = (img1 != nullptr && c >= 128)
                            ? (img1 + (c - 128) * M) : (img0 + c * M);
        cp16(aS[0] + pu0 * 16, srcA + m0 + lane * 8);
        cp16(aS[0] + pu1 * 16, srcA + m0 + lane * 8 + 4);
        const float* srcB = W + c * 256 + n0;
        cp16(bS[0] + pu0 * 16, srcB + lane * 8);
        cp16(bS[0] + pu1 * 16, srcB + lane * 8 + 4);
        CP_COMMIT();
    }

    const int ua0 = swz(2 * ty), ua1 = swz(2 * ty + 1);
    const int ub0 = swz(2 * tx), ub1 = swz(2 * tx + 1);

    for (int i = 0; i < nk; i++) {
        if (i + 1 < nk) {
            int c = (i + 1) * 16 + ch;
            const float* srcA = (img1 != nullptr && c >= 128)
                                ? (img1 + (c - 128) * M) : (img0 + c * M);
            int buf = (i + 1) & 1;
            cp16(aS[buf] + pu0 * 16, srcA + m0 + lane * 8);
            cp16(aS[buf] + pu1 * 16, srcA + m0 + lane * 8 + 4);
            const float* srcB = W + c * 256 + n0;
            cp16(bS[buf] + pu0 * 16, srcB + lane * 8);
            cp16(bS[buf] + pu1 * 16, srcB + lane * 8 + 4);
            CP_COMMIT();
            CP_WAIT(1);
        } else {
            CP_WAIT(0);
        }
        __syncthreads();
        const float* Ac = As[i & 1];
        const float* Bc = Bs[i & 1];
#pragma unroll
        for (int kk = 0; kk < 16; kk++) {
            ulonglong2 aA = *(const ulonglong2*)&Ac[kk * 128 + ua0 * 4];
            ulonglong2 aB = *(const ulonglong2*)&Ac[kk * 128 + ua1 * 4];
            ull a_pk[4] = {aA.x, aA.y, aB.x, aB.y};
            float4 bv0 = *(const float4*)&Bc[kk * 128 + ub0 * 4];
            float4 bv1 = *(const float4*)&Bc[kk * 128 + ub1 * 4];
            ull b_pk[8];
            b_pk[0] = pack2(bv0.x, bv0.x); b_pk[1] = pack2(bv0.y, bv0.y);
            b_pk[2] = pack2(bv0.z, bv0.z); b_pk[3] = pack2(bv0.w, bv0.w);
            b_pk[4] = pack2(bv1.x, bv1.x); b_pk[5] = pack2(bv1.y, bv1.y);
            b_pk[6] = pack2(bv1.z, bv1.z); b_pk[7] = pack2(bv1.w, bv1.w);
#pragma unroll
            for (int p = 0; p < 4; p++)
#pragma unroll
                for (int j = 0; j < 8; j++)
                    acc[p][j] = fma2(a_pk[p], b_pk[j], acc[p][j]);
        }
        __syncthreads();
    }

    // epilogue: 128x128 tile, rows m0+ty*8+2p+s, cols n0+tx*8..+7
#pragma unroll
    for (int p = 0; p < 4; p++) {
        float2 u[8];
#pragma unroll
        for (int j = 0; j < 8; j++) u[j] = unpack2(acc[p][j]);
        float* r0 = out + (m0 + ty * 8 + 2 * p) * 256 + n0 + tx * 8;
        float* r1 = r0 + 256;
        *(float4*)r0       = make_float4(u[0].x, u[1].x, u[2].x, u[3].x);
        *(float4*)(r0 + 4) = make_float4(u[4].x, u[5].x, u[6].x, u[7].x);
        *(float4*)r1       = make_float4(u[0].y, u[1].y, u[2].y, u[3].y);
        *(float4*)(r1 + 4) = make_float4(u[4].y, u[5].y, u[6].y, u[7].y);
    }
}

// ---------------------------------------------------------------------------
// Fused tail. One block = 32 consecutive HR points = 128 MLP rows.
//   layer2: D[128,128] = relu(h1)[128,256] @ W2  (f32x2, 8x8/thread)
//   layer3: C3[128,32] = relu(D+b2)[128,128] @ W3 (f32x2 GEMM, k-split 2)
//   blend:  softmax over 4 quadrants, channel-major store.
//
// smem byte map (106112 total):
//   phase A: As @0 (32x132 = 16896B), Bs @16896 (32x128 = 16384B, swz units),
//            hg @33280 (32x260 fp32 = 33280B)                end 66560
//   phase B: A3 @0 (128x132 = 67584B, swz units per k2)
//   W3s @67584 (16384B)  C3s @83968 (128x33 = 16896B)        end 100864
//   persistent @100864: w384 1024 | w385 @101888 1024 | b2s @102912 512 |
//     b3s @103424 128 | rely @103552 512 | relx @104064 512 |
//     gcs @104576 512 | wq @105088 512 | nbr @105600 512     end 106112
// ---------------------------------------------------------------------------
#define TAIL_SMEM_BYTES 106112

__global__ __launch_bounds__(256, 2) void fused_tail(
    const float* __restrict__ feat,
    const float* __restrict__ W1,
    const float* __restrict__ b1,
    const float* __restrict__ W2,
    const float* __restrict__ b2,
    const float* __restrict__ W3,
    const float* __restrict__ b3,
    float* __restrict__ out)
{
    extern __shared__ char smem[];
    float* As    = (float*)(smem);            // [kk][r] pitch 132 (phase A)
    float* Bs    = (float*)(smem + 16896);    // [kk][128], swizzled 16B units
    float* hg    = (float*)(smem + 33280);    // [pt][260] (phase A)
    float* A3    = (float*)(smem);            // [k2][132], swizzled units (phase B)
    float* W3s   = (float*)(smem + 67584);    // [k2][32]
    float* C3s   = (float*)(smem + 83968);    // [r][33]
    float* w384s = (float*)(smem + 100864);
    float* w385s = (float*)(smem + 101888);
    float* b2s   = (float*)(smem + 102912);
    float* b3s   = (float*)(smem + 103424);
    float* rely  = (float*)(smem + 103552);
    float* relx  = (float*)(smem + 104064);
    float* gcs   = (float*)(smem + 104576);
    float* wq    = (float*)(smem + 105088);
    int*   nbr   = (int*)  (smem + 105600);

    const int tid = threadIdx.x;
    const int p0  = blockIdx.x * 32;
    const int Y   = p0 >> 8;
    const int Xb  = p0 & 255;

    // small vectors (regions disjoint from phase A -> load now)
    w384s[tid] = W1[384 * 256 + tid];
    w385s[tid] = W1[385 * 256 + tid];
    if (tid < 128) b2s[tid] = b2[tid];
    if (tid < 32)  b3s[tid] = b3[tid];
#pragma unroll
    for (int i = 0; i < 16; i++) W3s[tid + 256 * i] = W3[tid + 256 * i];

    // per-row metadata + gating dots
    if (tid < 128) {
        int pt = tid >> 2, q = tid & 3;
        int X = Xb + pt;
        int vx = (q & 2) ? 1 : -1;        // perturbs Y (H axis)
        int vy = (q & 1) ? 1 : -1;        // perturbs X (W axis)
        int iy = (Y + vx) >> 1;           // exact nearest-sample reduction
        int ix = (X + vy) >> 1;
        bool ok = ((unsigned)iy < (unsigned)H_LR) && ((unsigned)ix < (unsigned)W_LR);
        int np = iy * W_LR + ix;
        nbr[tid]  = ok ? np : -1;
        rely[tid] = ok ? ((float)(Y - 2 * iy) - 0.5f) : ((float)Y + 0.5f - 128.0f);
        relx[tid] = ok ? ((float)(X - 2 * ix) - 0.5f) : ((float)X + 0.5f - 128.0f);
        float g = 0.f;
        if (ok) {
            int bp = (Y >> 1) * W_LR + (X >> 1);
#pragma unroll
            for (int c = 0; c < 3; c++)
                g = fmaf(feat[(124 + c) * NPIX_LR + bp],
                         feat[(124 + c) * NPIX_LR + np], g);
        }
        gcs[tid] = g;
    }

    // stage full hg (+b1) once: 32 pts x 256 k, pitch 260
#pragma unroll
    for (int i = 0; i < 8; i++) {
        int e = tid + 256 * i;            // float4 slots
        int pt = e >> 6, kq = (e & 63) * 4;
        float4 v = *(const float4*)&g_h1g[(p0 + pt) * 256 + kq];
        float4 bv = *(const float4*)&b1[kq];
        v.x += bv.x; v.y += bv.y; v.z += bv.z; v.w += bv.w;
        *(float4*)&hg[pt * 260 + kq] = v;
    }
    __syncthreads();

    if (tid < 32) {
        float g0 = gcs[tid * 4 + 0], g1 = gcs[tid * 4 + 1];
        float g2 = gcs[tid * 4 + 2], g3 = gcs[tid * 4 + 3];
        float m = fmaxf(fmaxf(g0, g1), fmaxf(g2, g3));
        float e0 = expf(g0 - m), e1 = expf(g1 - m), e2 = expf(g2 - m), e3 = expf(g3 - m);
        float inv = 1.0f / (e0 + e1 + e2 + e3);
        wq[tid * 4 + 0] = e0 * inv;
        wq[tid * 4 + 1] = e1 * inv;
        wq[tid * 4 + 2] = e2 * inv;
        wq[tid * 4 + 3] = e3 * inv;
    }

    // As-build thread mapping: one row per thread, half the k-chunk
    const int rB  = tid & 127;            // build row (warp spans 32 rows)
    const int khB = tid >> 7;             // k half (16 k's of the 32-chunk)
    const float ryB = rely[rB], rxB = relx[rB];
    const int nbB = nbr[rB];

    float4 pf[4];                          // prefetched g_h1f half-chunk
#pragma unroll
    for (int j = 0; j < 4; j++) pf[j] = make_float4(0.f, 0.f, 0.f, 0.f);
    if (nbB >= 0) {
        const float* fr = g_h1f + nbB * 256 + khB * 16;
#pragma unroll
        for (int j = 0; j < 4; j++) pf[j] = *(const float4*)&fr[j * 4];
    }

    // ---- layer 2: 8 chunks of K=32 ----
    const int tx = tid & 15, ty = tid >> 4;
    const int ub0 = swz(2 * tx), ub1 = swz(2 * tx + 1);
    ull acc[4][8];
#pragma unroll
    for (int i = 0; i < 4; i++)
#pragma unroll
        for (int j = 0; j < 8; j++) acc[i][j] = pack2(0.f, 0.f);

    for (int k0 = 0; k0 < 256; k0 += 32) {
        __syncthreads();                  // prev inner done reading As/Bs
        // build relu(h1) chunk: As[kk][rB], conflict-free STS
        {
            const float* hrow = hg + (rB >> 2) * 260 + k0 + khB * 16;
#pragma unroll
            for (int j = 0; j < 4; j++) {
                float4 h = *(const float4*)&hrow[j * 4];
                float4 f = pf[j];
#pragma unroll
                for (int t = 0; t < 4; t++) {
                    int kk = khB * 16 + j * 4 + t;
                    float v = (&h.x)[t] + (&f.x)[t];
                    v = fmaf(ryB, w384s[k0 + kk], v);
                    v = fmaf(rxB, w385s[k0 + kk], v);
                    As[kk * 132 + rB] = fmaxf(v, 0.f);
                }
            }
        }
        // stage W2 chunk with unit swizzle
#pragma unroll
        for (int i = 0; i < 4; i++) {
            int e = tid + 256 * i;
            int kk = e >> 5, u = e & 31;
            *(float4*)&Bs[kk * 128 + swz(u) * 4] =
                *(const float4*)&W2[(k0 + kk) * 128 + u * 4];
        }
        // prefetch next g_h1f half-chunk
        if (k0 < 224 && nbB >= 0) {
            const float* fr = g_h1f + nbB * 256 + k0 + 32 + khB * 16;
#pragma unroll
            for (int j = 0; j < 4; j++) pf[j] = *(const float4*)&fr[j * 4];
        }
        __syncthreads();                  // As/Bs visible
#pragma unroll
        for (int kk = 0; kk < 32; kk++) {
            ulonglong2 aA = *(const ulonglong2*)&As[kk * 132 + ty * 8];
            ulonglong2 aB = *(const ulonglong2*)&As[kk * 132 + ty * 8 + 4];
            ull a_pk[4] = {aA.x, aA.y, aB.x, aB.y};
            float4 bv0 = *(const float4*)&Bs[kk * 128 + ub0 * 4];
            float4 bv1 = *(const float4*)&Bs[kk * 128 + ub1 * 4];
            ull b_pk[8];
            b_pk[0] = pack2(bv0.x, bv0.x); b_pk[1] = pack2(bv0.y, bv0.y);
            b_pk[2] = pack2(bv0.z, bv0.z); b_pk[3] = pack2(bv0.w, bv0.w);
            b_pk[4] = pack2(bv1.x, bv1.x); b_pk[5] = pack2(bv1.y, bv1.y);
            b_pk[6] = pack2(bv1.z, bv1.z); b_pk[7] = pack2(bv1.w, bv1.w);
#pragma unroll
            for (int i = 0; i < 4; i++)
#pragma unroll
                for (int j = 0; j < 8; j++)
                    acc[i][j] = fma2(a_pk[i], b_pk[j], acc[i][j]);
        }
    }
    __syncthreads();                      // layer2 done; phase A smem free

    // relu(l2 + b2) -> A3 transposed [k2][r], 16B units swizzled by (k2>>3)&7
#pragma unroll
    for (int j = 0; j < 8; j++) {
        int k2 = tx * 8 + j;
        int sw = (k2 >> 3) & 7;
        float bb = b2s[k2];
#pragma unroll
        for (int i2 = 0; i2 < 4; i2++) {
            float2 u = unpack2(acc[i2][j]);
            float2 o;
            o.x = fmaxf(u.x + bb, 0.f);
            o.y = fmaxf(u.y + bb, 0.f);
            int ro = ty * 8 + 2 * i2;            // row offset within 128
            int ur = (ro >> 2) ^ sw;             // swizzled 16B unit
            int intra = ro & 3;
            *(float2*)&A3[k2 * 132 + ur * 4 + intra] = o;
        }
    }
    __syncthreads();

    // ---- layer 3: C3[128,32] = A3^T @ W3, k-split GEMM ----
    // 256 threads = kh(2) x rg(16) x cg(8); tile 8 rows x 4 cols per thread.
    {
        const int kh = tid >> 7;          // k-half
        const int rem = tid & 127;
        const int rg = rem >> 3;          // rows rg*8..+7
        const int cg = rem & 7;           // cols cg*4..+3
        ull a3[4][4];                     // [row pair][col]
#pragma unroll
        for (int p = 0; p < 4; p++)
#pragma unroll
            for (int j = 0; j < 4; j++) a3[p][j] = pack2(0.f, 0.f);

        const float* w_base = W3s + (uint32_t)kh * 64 * 32 + cg * 4;
        for (int kt = 0; kt < 64; kt++) {
            int k2 = kh * 64 + kt;
            int sw = (k2 >> 3) & 7;
            const float* arow = A3 + k2 * 132;
            ulonglong2 aA = *(const ulonglong2*)&arow[((2 * rg) ^ sw) * 4];
            ulonglong2 aB = *(const ulonglong2*)&arow[((2 * rg + 1) ^ sw) * 4];
            float4 wv = *(const float4*)(w_base + kt * 32);
            ull w0 = pack2(wv.x, wv.x), w1 = pack2(wv.y, wv.y);
            ull w2 = pack2(wv.z, wv.z), w3v = pack2(wv.w, wv.w);
            ull ap[4] = {aA.x, aA.y, aB.x, aB.y};
#pragma unroll
            for (int p = 0; p < 4; p++) {
                a3[p][0] = fma2(ap[p], w0, a3[p][0]);
                a3[p][1] = fma2(ap[p], w1, a3[p][1]);
                a3[p][2] = fma2(ap[p], w2, a3[p][2]);
                a3[p][3] = fma2(ap[p], w3v, a3[p][3]);
            }
        }
        // reduce two k-halves via C3s
        if (kh == 1) {
#pragma unroll
            for (int p = 0; p < 4; p++)
#pragma unroll
                for (int j = 0; j < 4; j++) {
                    float2 u = unpack2(a3[p][j]);
                    C3s[(rg * 8 + 2 * p) * 33 + cg * 4 + j]     = u.x;
                    C3s[(rg * 8 + 2 * p + 1) * 33 + cg * 4 + j] = u.y;
                }
        }
        __syncthreads();
        if (kh == 0) {
#pragma unroll
            for (int p = 0; p < 4; p++)
#pragma unroll
                for (int j = 0; j < 4; j++) {
                    float2 u = unpack2(a3[p][j]);
                    C3s[(rg * 8 + 2 * p) * 33 + cg * 4 + j]     += u.x;
                    C3s[(rg * 8 + 2 * p + 1) * 33 + cg * 4 + j] += u.y;
                }
        }
        __syncthreads();
    }

    // ---- softmax blend + coalesced channel-major store ----
#pragma unroll
    for (int i = 0; i < 4; i++) {
        int idx = tid + 256 * i;
        int pt = idx & 31, n = idx >> 5;
        float s = b3s[n];                 // sum(w)=1 -> bias post-blend
#pragma unroll
        for (int q = 0; q < 4; q++)
            s = fmaf(wq[pt * 4 + q], C3s[(pt * 4 + q) * 33 + n], s);
        out[n * NPTS + p0 + pt] = s;
    }
}

// ---------------------------------------------------------------------------
extern "C" void kernel_launch(void* const* d_in, const int* in_sizes, int n_in,
                              void* d_out, int out_size)
{
    const float* feat     = (const float*)d_in[0];
    const float* lr_guide = (const float*)d_in[1];
    const float* hr_guide = (const float*)d_in[2];
    const float* W1       = (const float*)d_in[3];
    const float* b1       = (const float*)d_in[4];
    const float* W2       = (const float*)d_in[5];
    const float* b2       = (const float*)d_in[6];
    const float* W3       = (const float*)d_in[7];
    const float* b3       = (const float*)d_in[8];
    float* out = (float*)d_out;

    void* h1f_p = nullptr;
    void* h1g_p = nullptr;
    cudaGetSymbolAddress(&h1f_p, g_h1f);
    cudaGetSymbolAddress(&h1g_p, g_h1g);

    // h1_feat[16384,256] = featc_T @ W1[0:256,:]
    {
        dim3 grid(NPIX_LR / 128, 256 / 128);
        gemm_layer1<<<grid, 256>>>(lr_guide, feat, W1, (float*)h1f_p, NPIX_LR, 256);
    }
    // h1_guide[65536,256] = hr_guide_T @ W1[256:384,:]
    {
        dim3 grid(NPTS / 128, 256 / 128);
        gemm_layer1<<<grid, 256>>>(hr_guide, nullptr, W1 + 256 * 256, (float*)h1g_p,
                                   NPTS, 128);
    }
    // fused tail
    {
        cudaFuncSetAttribute(fused_tail, cudaFuncAttributeMaxDynamicSharedMemorySize,
                             TAIL_SMEM_BYTES);
        fused_tail<<<NPTS / 32, 256, TAIL_SMEM_BYTES>>>(
            feat, W1, b1, W2, b2, W3, b3, out);
    }
}